// round 2
// baseline (speedup 1.0000x reference)
#include <cuda_runtime.h>
#include <cuda_bf16.h>
#include <stdint.h>
#include <math.h>

// Problem constants
#define NTOK 4096        // B*T
#define DD   1024        // model dim
#define EE   8           // experts
#define HH   2048        // expert hidden
#define CAP  4096        // max tokens per expert (top-k indices distinct -> <= NTOK)
#define LDA  40          // smem row stride in bf16 (32 + 8 pad, keeps 16B alignment)

// ---------------- static scratch (no allocations allowed) ----------------
__device__ int   g_cnt[EE];
__device__ int   g_tok[EE * CAP];
__device__ float g_gate[EE * CAP];
__device__ int   g_dst[EE * CAP];
// split-bf16 operands: v = hi + lo  (lo = bf16(v - hi)), ~16 effective mantissa bits
__device__ __nv_bfloat16 g_xh[(size_t)NTOK * DD];
__device__ __nv_bfloat16 g_xl[(size_t)NTOK * DD];
__device__ __nv_bfloat16 g_w1h[(size_t)EE * DD * HH];
__device__ __nv_bfloat16 g_w1l[(size_t)EE * DD * HH];
__device__ __nv_bfloat16 g_w2h[(size_t)EE * HH * DD];
__device__ __nv_bfloat16 g_w2l[(size_t)EE * HH * DD];
__device__ __nv_bfloat16 g_hh[(size_t)EE * CAP * HH];
__device__ __nv_bfloat16 g_hl[(size_t)EE * CAP * HH];
__device__ float g_y[(size_t)NTOK * 2 * DD];

// ---------------- tiny kernels ----------------
__global__ void k_zero() {
    if (threadIdx.x < EE) g_cnt[threadIdx.x] = 0;
}

__device__ __forceinline__ void split2(float a, float b, uint32_t& hi, uint32_t& lo) {
    __nv_bfloat16 ha = __float2bfloat16_rn(a);
    __nv_bfloat16 hb = __float2bfloat16_rn(b);
    __nv_bfloat16 la = __float2bfloat16_rn(a - __bfloat162float(ha));
    __nv_bfloat16 lb = __float2bfloat16_rn(b - __bfloat162float(hb));
    __nv_bfloat162 ph = __halves2bfloat162(ha, hb);
    __nv_bfloat162 pl = __halves2bfloat162(la, lb);
    hi = *reinterpret_cast<uint32_t*>(&ph);
    lo = *reinterpret_cast<uint32_t*>(&pl);
}

// Convert fp32 -> (hi, lo) bf16 pair arrays. which: 0=x, 1=W1, 2=W2
__global__ void k_cvt2(const float* __restrict__ src, int which, int n4) {
    __nv_bfloat16 *hi, *lo;
    if (which == 0)      { hi = g_xh;  lo = g_xl;  }
    else if (which == 1) { hi = g_w1h; lo = g_w1l; }
    else                 { hi = g_w2h; lo = g_w2l; }
    int i = blockIdx.x * blockDim.x + threadIdx.x;
    int stride = gridDim.x * blockDim.x;
    for (; i < n4; i += stride) {
        float4 v = reinterpret_cast<const float4*>(src)[i];
        uint2 oh, ol;
        split2(v.x, v.y, oh.x, ol.x);
        split2(v.z, v.w, oh.y, ol.y);
        reinterpret_cast<uint2*>(hi)[i] = oh;
        reinterpret_cast<uint2*>(lo)[i] = ol;
    }
}

// Router: one block (256 thr = 8 warps) per token; warp w computes logit for expert w.
__global__ void k_router(const float* __restrict__ x, const float* __restrict__ Wr,
                         const float* __restrict__ br) {
    const int t = blockIdx.x;
    const int lane = threadIdx.x & 31, w = threadIdx.x >> 5;
    const float* xr = x + (size_t)t * DD;
    float s = 0.f;
    for (int d = lane; d < DD; d += 32) s = fmaf(xr[d], Wr[d * EE + w], s);
    #pragma unroll
    for (int o = 16; o; o >>= 1) s += __shfl_xor_sync(0xffffffffu, s, o);
    __shared__ float lg[EE];
    if (lane == 0) lg[w] = s + br[w];
    __syncthreads();
    if (threadIdx.x == 0) {
        // top-2 with lowest-index tie-break (matches jax.lax.top_k)
        float v0 = -3.4e38f; int i0 = 0;
        #pragma unroll
        for (int e = 0; e < EE; e++) if (lg[e] > v0) { v0 = lg[e]; i0 = e; }
        float v1 = -3.4e38f; int i1 = 0;
        #pragma unroll
        for (int e = 0; e < EE; e++) if (e != i0 && lg[e] > v1) { v1 = lg[e]; i1 = e; }
        float eb  = expf(v1 - v0);
        float inv = 1.f / (1.f + eb);
        float g0 = inv, g1 = eb * inv;
        int p0 = atomicAdd(&g_cnt[i0], 1);
        g_tok[i0 * CAP + p0] = t; g_gate[i0 * CAP + p0] = g0; g_dst[i0 * CAP + p0] = 2 * t;
        int p1 = atomicAdd(&g_cnt[i1], 1);
        g_tok[i1 * CAP + p1] = t; g_gate[i1 * CAP + p1] = g1; g_dst[i1 * CAP + p1] = 2 * t + 1;
    }
}

// ---------------- mma helper ----------------
__device__ __forceinline__ void mma_bf16(float c[4], const uint32_t a[4], const uint32_t b[2]) {
    asm volatile(
        "mma.sync.aligned.m16n8k16.row.col.f32.bf16.bf16.f32 "
        "{%0,%1,%2,%3}, {%4,%5,%6,%7}, {%8,%9}, {%0,%1,%2,%3};\n"
        : "+f"(c[0]), "+f"(c[1]), "+f"(c[2]), "+f"(c[3])
        : "r"(a[0]), "r"(a[1]), "r"(a[2]), "r"(a[3]), "r"(b[0]), "r"(b[1]));
}

// GEMM1: H[m, n] = relu( Xg[m, :] @ W1[e][:, n] + b1[e][n] ), split-bf16 triple MMA.
// Block tile 64x64, 128 threads (4 warps in 2x2), k-step 32.
__global__ __launch_bounds__(128) void k_gemm1(const float* __restrict__ b1) {
    const int e   = blockIdx.z;
    const int cnt = g_cnt[e];
    const int mb  = blockIdx.y * 64;
    if (mb >= cnt) return;
    const int nb  = blockIdx.x * 64;

    __shared__ __nv_bfloat16 Ash[64 * LDA];
    __shared__ __nv_bfloat16 Asl[64 * LDA];
    __shared__ __nv_bfloat16 Bsh[64 * LDA];
    __shared__ __nv_bfloat16 Bsl[64 * LDA];
    __shared__ int stok[64];

    const int tid = threadIdx.x;
    if (tid < 64) {
        int m = mb + tid;
        stok[tid] = (m < cnt) ? g_tok[e * CAP + m] : -1;
    }
    __syncthreads();

    const int w = tid >> 5, lane = tid & 31;
    const int wm = (w >> 1) * 32, wn = (w & 1) * 32;
    const int g = lane >> 2, tq = lane & 3;

    float acc[2][4][4];
    #pragma unroll
    for (int a = 0; a < 2; a++)
        #pragma unroll
        for (int b = 0; b < 4; b++)
            #pragma unroll
            for (int c = 0; c < 4; c++) acc[a][b][c] = 0.f;

    const __nv_bfloat16* wph = g_w1h + (size_t)e * DD * HH;
    const __nv_bfloat16* wpl = g_w1l + (size_t)e * DD * HH;

    for (int kt = 0; kt < DD; kt += 32) {
        // A tiles: 64 rows x 32 k (gathered token rows), k-contiguous
        #pragma unroll
        for (int r = 0; r < 2; r++) {
            int i = tid + r * 128;
            int row = i >> 2, kc = (i & 3) * 8;
            uint4 vh = make_uint4(0u, 0u, 0u, 0u), vl = vh;
            int tok = stok[row];
            if (tok >= 0) {
                size_t off = (size_t)tok * DD + kt + kc;
                vh = *reinterpret_cast<const uint4*>(&g_xh[off]);
                vl = *reinterpret_cast<const uint4*>(&g_xl[off]);
            }
            *reinterpret_cast<uint4*>(&Ash[row * LDA + kc]) = vh;
            *reinterpret_cast<uint4*>(&Asl[row * LDA + kc]) = vl;
        }
        // B tiles: W1 is [k][n] n-contig; transpose into Bs[n][k]
        #pragma unroll
        for (int r = 0; r < 2; r++) {
            int i = tid + r * 128;
            int kr = i >> 3, nc = (i & 7) * 8;
            size_t off = (size_t)(kt + kr) * HH + nb + nc;
            uint4 vh = *reinterpret_cast<const uint4*>(&wph[off]);
            uint4 vl = *reinterpret_cast<const uint4*>(&wpl[off]);
            __nv_bfloat16 th[8], tl[8];
            *reinterpret_cast<uint4*>(th) = vh;
            *reinterpret_cast<uint4*>(tl) = vl;
            #pragma unroll
            for (int j = 0; j < 8; j++) {
                Bsh[(nc + j) * LDA + kr] = th[j];
                Bsl[(nc + j) * LDA + kr] = tl[j];
            }
        }
        __syncthreads();
        #pragma unroll
        for (int kk = 0; kk < 32; kk += 16) {
            uint32_t ah[2][4], al[2][4], bh[4][2], bl[4][2];
            #pragma unroll
            for (int mf = 0; mf < 2; mf++) {
                int r0 = wm + mf * 16;
                #pragma unroll
                for (int q = 0; q < 4; q++) {
                    int row = r0 + g + ((q & 1) ? 8 : 0);
                    int col = kk + ((q & 2) ? 8 : 0) + 2 * tq;
                    ah[mf][q] = *reinterpret_cast<const uint32_t*>(&Ash[row * LDA + col]);
                    al[mf][q] = *reinterpret_cast<const uint32_t*>(&Asl[row * LDA + col]);
                }
            }
            #pragma unroll
            for (int nf = 0; nf < 4; nf++) {
                int c0 = wn + nf * 8 + g;
                bh[nf][0] = *reinterpret_cast<const uint32_t*>(&Bsh[c0 * LDA + kk + 2 * tq]);
                bh[nf][1] = *reinterpret_cast<const uint32_t*>(&Bsh[c0 * LDA + kk + 8 + 2 * tq]);
                bl[nf][0] = *reinterpret_cast<const uint32_t*>(&Bsl[c0 * LDA + kk + 2 * tq]);
                bl[nf][1] = *reinterpret_cast<const uint32_t*>(&Bsl[c0 * LDA + kk + 8 + 2 * tq]);
            }
            #pragma unroll
            for (int mf = 0; mf < 2; mf++)
                #pragma unroll
                for (int nf = 0; nf < 4; nf++) {
                    mma_bf16(acc[mf][nf], ah[mf], bh[nf]);
                    mma_bf16(acc[mf][nf], ah[mf], bl[nf]);
                    mma_bf16(acc[mf][nf], al[mf], bh[nf]);
                }
        }
        __syncthreads();
    }

    // epilogue: +b1, relu, split-store bf16 hi/lo into H scratch
    #pragma unroll
    for (int mf = 0; mf < 2; mf++) {
        #pragma unroll
        for (int rr = 0; rr < 2; rr++) {
            int m = mb + wm + mf * 16 + g + rr * 8;
            if (m >= cnt) continue;
            size_t base = ((size_t)e * CAP + m) * HH + nb;
            #pragma unroll
            for (int nf = 0; nf < 4; nf++) {
                int c = wn + nf * 8 + 2 * tq;
                float v0 = fmaxf(acc[mf][nf][rr * 2 + 0] + b1[e * HH + nb + c], 0.f);
                float v1 = fmaxf(acc[mf][nf][rr * 2 + 1] + b1[e * HH + nb + c + 1], 0.f);
                uint32_t ph, pl;
                split2(v0, v1, ph, pl);
                *reinterpret_cast<uint32_t*>(&g_hh[base + c]) = ph;
                *reinterpret_cast<uint32_t*>(&g_hl[base + c]) = pl;
            }
        }
    }
}

// GEMM2: Y[dst(m), n] = gate(m) * ( H[m, :] @ W2[e][:, n] + b2[e][n] ), split-bf16 triple MMA.
__global__ __launch_bounds__(128) void k_gemm2(const float* __restrict__ b2) {
    const int e   = blockIdx.z;
    const int cnt = g_cnt[e];
    const int mb  = blockIdx.y * 64;
    if (mb >= cnt) return;
    const int nb  = blockIdx.x * 64;

    __shared__ __nv_bfloat16 Ash[64 * LDA];
    __shared__ __nv_bfloat16 Asl[64 * LDA];
    __shared__ __nv_bfloat16 Bsh[64 * LDA];
    __shared__ __nv_bfloat16 Bsl[64 * LDA];

    const int tid = threadIdx.x;
    const int w = tid >> 5, lane = tid & 31;
    const int wm = (w >> 1) * 32, wn = (w & 1) * 32;
    const int g = lane >> 2, tq = lane & 3;

    float acc[2][4][4];
    #pragma unroll
    for (int a = 0; a < 2; a++)
        #pragma unroll
        for (int b = 0; b < 4; b++)
            #pragma unroll
            for (int c = 0; c < 4; c++) acc[a][b][c] = 0.f;

    const __nv_bfloat16* aph = g_hh + ((size_t)e * CAP + mb) * HH;
    const __nv_bfloat16* apl = g_hl + ((size_t)e * CAP + mb) * HH;
    const __nv_bfloat16* wph = g_w2h + (size_t)e * HH * DD;
    const __nv_bfloat16* wpl = g_w2l + (size_t)e * HH * DD;

    for (int kt = 0; kt < HH; kt += 32) {
        #pragma unroll
        for (int r = 0; r < 2; r++) {
            int i = tid + r * 128;
            int row = i >> 2, kc = (i & 3) * 8;
            size_t off = (size_t)row * HH + kt + kc;
            // rows >= cnt contain stale-but-finite data; their outputs are never stored
            *reinterpret_cast<uint4*>(&Ash[row * LDA + kc]) =
                *reinterpret_cast<const uint4*>(&aph[off]);
            *reinterpret_cast<uint4*>(&Asl[row * LDA + kc]) =
                *reinterpret_cast<const uint4*>(&apl[off]);
        }
        #pragma unroll
        for (int r = 0; r < 2; r++) {
            int i = tid + r * 128;
            int kr = i >> 3, nc = (i & 7) * 8;
            size_t off = (size_t)(kt + kr) * DD + nb + nc;
            uint4 vh = *reinterpret_cast<const uint4*>(&wph[off]);
            uint4 vl = *reinterpret_cast<const uint4*>(&wpl[off]);
            __nv_bfloat16 th[8], tl[8];
            *reinterpret_cast<uint4*>(th) = vh;
            *reinterpret_cast<uint4*>(tl) = vl;
            #pragma unroll
            for (int j = 0; j < 8; j++) {
                Bsh[(nc + j) * LDA + kr] = th[j];
                Bsl[(nc + j) * LDA + kr] = tl[j];
            }
        }
        __syncthreads();
        #pragma unroll
        for (int kk = 0; kk < 32; kk += 16) {
            uint32_t ah[2][4], al[2][4], bh[4][2], bl[4][2];
            #pragma unroll
            for (int mf = 0; mf < 2; mf++) {
                int r0 = wm + mf * 16;
                #pragma unroll
                for (int q = 0; q < 4; q++) {
                    int row = r0 + g + ((q & 1) ? 8 : 0);
                    int col = kk + ((q & 2) ? 8 : 0) + 2 * tq;
                    ah[mf][q] = *reinterpret_cast<const uint32_t*>(&Ash[row * LDA + col]);
                    al[mf][q] = *reinterpret_cast<const uint32_t*>(&Asl[row * LDA + col]);
                }
            }
            #pragma unroll
            for (int nf = 0; nf < 4; nf++) {
                int c0 = wn + nf * 8 + g;
                bh[nf][0] = *reinterpret_cast<const uint32_t*>(&Bsh[c0 * LDA + kk + 2 * tq]);
                bh[nf][1] = *reinterpret_cast<const uint32_t*>(&Bsh[c0 * LDA + kk + 8 + 2 * tq]);
                bl[nf][0] = *reinterpret_cast<const uint32_t*>(&Bsl[c0 * LDA + kk + 2 * tq]);
                bl[nf][1] = *reinterpret_cast<const uint32_t*>(&Bsl[c0 * LDA + kk + 8 + 2 * tq]);
            }
            #pragma unroll
            for (int mf = 0; mf < 2; mf++)
                #pragma unroll
                for (int nf = 0; nf < 4; nf++) {
                    mma_bf16(acc[mf][nf], ah[mf], bh[nf]);
                    mma_bf16(acc[mf][nf], ah[mf], bl[nf]);
                    mma_bf16(acc[mf][nf], al[mf], bh[nf]);
                }
        }
        __syncthreads();
    }

    // epilogue: +b2, * gate, store fp32 row into Y scratch at the (token, k-slot) row
    #pragma unroll
    for (int mf = 0; mf < 2; mf++) {
        #pragma unroll
        for (int rr = 0; rr < 2; rr++) {
            int m = mb + wm + mf * 16 + g + rr * 8;
            if (m >= cnt) continue;
            float gate = g_gate[e * CAP + m];
            int   dst  = g_dst[e * CAP + m];
            float* yrow = g_y + (size_t)dst * DD + nb;
            #pragma unroll
            for (int nf = 0; nf < 4; nf++) {
                int c = wn + nf * 8 + 2 * tq;
                float2 pr;
                pr.x = (acc[mf][nf][rr * 2 + 0] + b2[e * DD + nb + c]) * gate;
                pr.y = (acc[mf][nf][rr * 2 + 1] + b2[e * DD + nb + c + 1]) * gate;
                *reinterpret_cast<float2*>(&yrow[c]) = pr;
            }
        }
    }
}

__global__ void k_combine(float* __restrict__ out) {
    int i = blockIdx.x * blockDim.x + threadIdx.x;   // exact grid: NTOK*DD threads
    int t = i >> 10;           // / DD
    int d = i & (DD - 1);
    out[i] = g_y[(size_t)(2 * t) * DD + d] + g_y[(size_t)(2 * t + 1) * DD + d];
}

// ---------------- launch ----------------
extern "C" void kernel_launch(void* const* d_in, const int* in_sizes, int n_in,
                              void* d_out, int out_size) {
    const float* x  = (const float*)d_in[0];
    const float* Wr = (const float*)d_in[1];
    const float* br = (const float*)d_in[2];
    const float* W1 = (const float*)d_in[3];
    const float* b1 = (const float*)d_in[4];
    const float* W2 = (const float*)d_in[5];
    const float* b2 = (const float*)d_in[6];
    float* out = (float*)d_out;

    k_zero<<<1, 32>>>();
    k_cvt2<<<2048, 256>>>(x,  0, NTOK * DD / 4);
    k_cvt2<<<8192, 256>>>(W1, 1, EE * DD * HH / 4);
    k_cvt2<<<8192, 256>>>(W2, 2, EE * HH * DD / 4);
    k_router<<<NTOK, 256>>>(x, Wr, br);
    k_gemm1<<<dim3(HH / 64, CAP / 64, EE), 128>>>(b1);
    k_gemm2<<<dim3(DD / 64, CAP / 64, EE), 128>>>(b2);
    k_combine<<<(NTOK * DD) / 256, 256>>>(out);
}

// round 3
// speedup vs baseline: 1.9687x; 1.9687x over previous
#include <cuda_runtime.h>
#include <cuda_bf16.h>
#include <stdint.h>
#include <math.h>

// Problem constants
#define NTOK 4096        // B*T
#define DD   1024        // model dim
#define EE   8           // experts
#define HH   2048        // expert hidden
#define CAP  4096        // max tokens per expert

// GEMM tiling
#define BM 128
#define BN 64
#define BK 16
#define LDAS 24          // BK + 8 pad (bf16 elems); 48B rows -> ldmatrix-aligned
#define LDBS 72          // BN + 8 pad; 144B rows -> ldmatrix-aligned
#define NT 256

// ---------------- static scratch (no allocations allowed) ----------------
__device__ int   g_cnt[EE];
__device__ int   g_tok[EE * CAP];
__device__ float g_gate[EE * CAP];
__device__ int   g_dst[EE * CAP];
// split-bf16 operands: v = hi + lo  (lo = bf16(v - hi)), ~16 effective mantissa bits
__device__ __nv_bfloat16 g_xh[(size_t)NTOK * DD];
__device__ __nv_bfloat16 g_xl[(size_t)NTOK * DD];
__device__ __nv_bfloat16 g_w1h[(size_t)EE * DD * HH];
__device__ __nv_bfloat16 g_w1l[(size_t)EE * DD * HH];
__device__ __nv_bfloat16 g_w2h[(size_t)EE * HH * DD];
__device__ __nv_bfloat16 g_w2l[(size_t)EE * HH * DD];
__device__ __nv_bfloat16 g_hh[(size_t)EE * CAP * HH];
__device__ __nv_bfloat16 g_hl[(size_t)EE * CAP * HH];
__device__ float g_y[(size_t)NTOK * 2 * DD];

// ---------------- tiny kernels ----------------
__global__ void k_zero() {
    if (threadIdx.x < EE) g_cnt[threadIdx.x] = 0;
}

__device__ __forceinline__ void split2(float a, float b, uint32_t& hi, uint32_t& lo) {
    __nv_bfloat16 ha = __float2bfloat16_rn(a);
    __nv_bfloat16 hb = __float2bfloat16_rn(b);
    __nv_bfloat16 la = __float2bfloat16_rn(a - __bfloat162float(ha));
    __nv_bfloat16 lb = __float2bfloat16_rn(b - __bfloat162float(hb));
    __nv_bfloat162 ph = __halves2bfloat162(ha, hb);
    __nv_bfloat162 pl = __halves2bfloat162(la, lb);
    hi = *reinterpret_cast<uint32_t*>(&ph);
    lo = *reinterpret_cast<uint32_t*>(&pl);
}

__global__ void k_cvt2(const float* __restrict__ src, int which, int n4) {
    __nv_bfloat16 *hi, *lo;
    if (which == 0)      { hi = g_xh;  lo = g_xl;  }
    else if (which == 1) { hi = g_w1h; lo = g_w1l; }
    else                 { hi = g_w2h; lo = g_w2l; }
    int i = blockIdx.x * blockDim.x + threadIdx.x;
    int stride = gridDim.x * blockDim.x;
    for (; i < n4; i += stride) {
        float4 v = reinterpret_cast<const float4*>(src)[i];
        uint2 oh, ol;
        split2(v.x, v.y, oh.x, ol.x);
        split2(v.z, v.w, oh.y, ol.y);
        reinterpret_cast<uint2*>(hi)[i] = oh;
        reinterpret_cast<uint2*>(lo)[i] = ol;
    }
}

__global__ void k_router(const float* __restrict__ x, const float* __restrict__ Wr,
                         const float* __restrict__ br) {
    const int t = blockIdx.x;
    const int lane = threadIdx.x & 31, w = threadIdx.x >> 5;
    const float* xr = x + (size_t)t * DD;
    float s = 0.f;
    for (int d = lane; d < DD; d += 32) s = fmaf(xr[d], Wr[d * EE + w], s);
    #pragma unroll
    for (int o = 16; o; o >>= 1) s += __shfl_xor_sync(0xffffffffu, s, o);
    __shared__ float lg[EE];
    if (lane == 0) lg[w] = s + br[w];
    __syncthreads();
    if (threadIdx.x == 0) {
        float v0 = -3.4e38f; int i0 = 0;
        #pragma unroll
        for (int e = 0; e < EE; e++) if (lg[e] > v0) { v0 = lg[e]; i0 = e; }
        float v1 = -3.4e38f; int i1 = 0;
        #pragma unroll
        for (int e = 0; e < EE; e++) if (e != i0 && lg[e] > v1) { v1 = lg[e]; i1 = e; }
        float eb  = expf(v1 - v0);
        float inv = 1.f / (1.f + eb);
        float g0 = inv, g1 = eb * inv;
        int p0 = atomicAdd(&g_cnt[i0], 1);
        g_tok[i0 * CAP + p0] = t; g_gate[i0 * CAP + p0] = g0; g_dst[i0 * CAP + p0] = 2 * t;
        int p1 = atomicAdd(&g_cnt[i1], 1);
        g_tok[i1 * CAP + p1] = t; g_gate[i1 * CAP + p1] = g1; g_dst[i1 * CAP + p1] = 2 * t + 1;
    }
}

// ---------------- asm helpers ----------------
__device__ __forceinline__ void mma_bf16(float c[4], const uint32_t a[4], const uint32_t b[2]) {
    asm volatile(
        "mma.sync.aligned.m16n8k16.row.col.f32.bf16.bf16.f32 "
        "{%0,%1,%2,%3}, {%4,%5,%6,%7}, {%8,%9}, {%0,%1,%2,%3};\n"
        : "+f"(c[0]), "+f"(c[1]), "+f"(c[2]), "+f"(c[3])
        : "r"(a[0]), "r"(a[1]), "r"(a[2]), "r"(a[3]), "r"(b[0]), "r"(b[1]));
}
__device__ __forceinline__ void ldsm_x4(uint32_t r[4], uint32_t addr) {
    asm volatile("ldmatrix.sync.aligned.m8n8.x4.shared.b16 {%0,%1,%2,%3}, [%4];\n"
        : "=r"(r[0]), "=r"(r[1]), "=r"(r[2]), "=r"(r[3]) : "r"(addr));
}
__device__ __forceinline__ void ldsm_x4_t(uint32_t r[4], uint32_t addr) {
    asm volatile("ldmatrix.sync.aligned.m8n8.x4.trans.shared.b16 {%0,%1,%2,%3}, [%4];\n"
        : "=r"(r[0]), "=r"(r[1]), "=r"(r[2]), "=r"(r[3]) : "r"(addr));
}
__device__ __forceinline__ void cp16(uint32_t dst, const void* src) {
    asm volatile("cp.async.cg.shared.global [%0], [%1], 16;\n" :: "r"(dst), "l"(src));
}
__device__ __forceinline__ void cp16z(uint32_t dst, const void* src, uint32_t sz) {
    asm volatile("cp.async.cg.shared.global [%0], [%1], 16, %2;\n" :: "r"(dst), "l"(src), "r"(sz));
}
#define CP_COMMIT() asm volatile("cp.async.commit_group;\n")

// ---------------- GEMM1: H = relu(Xg @ W1 + b1), split-bf16 triple MMA ----------------
__global__ __launch_bounds__(NT, 2) void k_gemm1(const float* __restrict__ b1) {
    const int e   = blockIdx.z;
    const int cnt = g_cnt[e];
    const int mb  = blockIdx.y * BM;
    if (mb >= cnt) return;
    const int nb  = blockIdx.x * BN;

    __shared__ __nv_bfloat16 Ash[2][BM * LDAS];
    __shared__ __nv_bfloat16 Asl[2][BM * LDAS];
    __shared__ __nv_bfloat16 Bsh[2][BK * LDBS];
    __shared__ __nv_bfloat16 Bsl[2][BK * LDBS];
    __shared__ int stok[BM];

    const int tid = threadIdx.x;
    if (tid < BM) {
        int m = mb + tid;
        stok[tid] = (m < cnt) ? g_tok[e * CAP + m] : -1;
    }
    __syncthreads();

    // loader coords: A: 2 thr/row (16B each); B: 8 thr/row, tid<128 hi / >=128 lo
    const int a_row = tid >> 1;
    const int a_col = (tid & 1) * 8;
    const int b_kr  = (tid & 127) >> 3;
    const int b_nc  = (tid & 7) * 8;
    const int atok  = stok[a_row];
    const uint32_t a_sz = (atok >= 0) ? 16u : 0u;
    const __nv_bfloat16* agh = g_xh + (atok >= 0 ? (size_t)atok * DD + a_col : 0);
    const __nv_bfloat16* agl = g_xl + (atok >= 0 ? (size_t)atok * DD + a_col : 0);
    const __nv_bfloat16* wbh = g_w1h + (size_t)e * DD * HH + (size_t)b_kr * HH + nb + b_nc;
    const __nv_bfloat16* wbl = g_w1l + (size_t)e * DD * HH + (size_t)b_kr * HH + nb + b_nc;

    const uint32_t sAh = (uint32_t)__cvta_generic_to_shared(&Ash[0][0]);
    const uint32_t sAl = (uint32_t)__cvta_generic_to_shared(&Asl[0][0]);
    const uint32_t sBh = (uint32_t)__cvta_generic_to_shared(&Bsh[0][0]);
    const uint32_t sBl = (uint32_t)__cvta_generic_to_shared(&Bsl[0][0]);
    const uint32_t aoff = (a_row * LDAS + a_col) * 2;
    const uint32_t boff = (b_kr * LDBS + b_nc) * 2;

    // fragment coords
    const int w = tid >> 5, lane = tid & 31;
    const int wm = (w >> 1) * 32, wn = (w & 1) * 32;
    const int g = lane >> 2, tq = lane & 3;
    const int lr = (lane & 7) + ((lane >> 3) & 1) * 8;
    const int lc = ((lane >> 4) & 1) * 8;
    const uint32_t aA0 = ((wm + lr) * LDAS + lc) * 2;
    const uint32_t aA1 = ((wm + 16 + lr) * LDAS + lc) * 2;
    const uint32_t bA0 = (lr * LDBS + wn + lc) * 2;
    const uint32_t bA1 = (lr * LDBS + wn + 16 + lc) * 2;

    float acc[2][4][4];
    #pragma unroll
    for (int a = 0; a < 2; a++)
        #pragma unroll
        for (int b = 0; b < 4; b++)
            #pragma unroll
            for (int c = 0; c < 4; c++) acc[a][b][c] = 0.f;

    const int NS = DD / BK;
    // prefetch stage 0
    {
        cp16z(sAh + aoff, agh, a_sz);
        cp16z(sAl + aoff, agl, a_sz);
        if (tid < 128) cp16(sBh + boff, wbh);
        else           cp16(sBl + boff, wbl);
        CP_COMMIT();
    }
    for (int s = 0; s < NS; s++) {
        const int b = s & 1;
        if (s + 1 < NS) {
            const int kt = (s + 1) * BK;
            const uint32_t ao = (b ^ 1) * (BM * LDAS * 2) + aoff;
            const uint32_t bo = (b ^ 1) * (BK * LDBS * 2) + boff;
            cp16z(sAh + ao, agh + kt, a_sz);
            cp16z(sAl + ao, agl + kt, a_sz);
            if (tid < 128) cp16(sBh + bo, wbh + (size_t)kt * HH);
            else           cp16(sBl + bo, wbl + (size_t)kt * HH);
            CP_COMMIT();
            asm volatile("cp.async.wait_group 1;\n");
        } else {
            asm volatile("cp.async.wait_group 0;\n");
        }
        __syncthreads();

        uint32_t ah[2][4], al[2][4], bh[2][4], bl[2][4];
        const uint32_t Ab  = sAh + b * (BM * LDAS * 2);
        const uint32_t Alb = sAl + b * (BM * LDAS * 2);
        const uint32_t Bb  = sBh + b * (BK * LDBS * 2);
        const uint32_t Blb = sBl + b * (BK * LDBS * 2);
        ldsm_x4(ah[0], Ab + aA0);
        ldsm_x4(ah[1], Ab + aA1);
        ldsm_x4(al[0], Alb + aA0);
        ldsm_x4(al[1], Alb + aA1);
        ldsm_x4_t(bh[0], Bb + bA0);
        ldsm_x4_t(bh[1], Bb + bA1);
        ldsm_x4_t(bl[0], Blb + bA0);
        ldsm_x4_t(bl[1], Blb + bA1);

        #pragma unroll
        for (int mf = 0; mf < 2; mf++)
            #pragma unroll
            for (int nf = 0; nf < 4; nf++) {
                const uint32_t* bph = &bh[nf >> 1][(nf & 1) * 2];
                const uint32_t* bpl = &bl[nf >> 1][(nf & 1) * 2];
                mma_bf16(acc[mf][nf], ah[mf], bph);
                mma_bf16(acc[mf][nf], ah[mf], bpl);
                mma_bf16(acc[mf][nf], al[mf], bph);
            }
        __syncthreads();
    }

    // epilogue: +b1, relu, split-store hi/lo
    #pragma unroll
    for (int mf = 0; mf < 2; mf++) {
        #pragma unroll
        for (int rr = 0; rr < 2; rr++) {
            int m = mb + wm + mf * 16 + g + rr * 8;
            if (m >= cnt) continue;
            size_t base = ((size_t)e * CAP + m) * HH + nb;
            #pragma unroll
            for (int nf = 0; nf < 4; nf++) {
                int c = wn + nf * 8 + 2 * tq;
                float v0 = fmaxf(acc[mf][nf][rr * 2 + 0] + b1[e * HH + nb + c], 0.f);
                float v1 = fmaxf(acc[mf][nf][rr * 2 + 1] + b1[e * HH + nb + c + 1], 0.f);
                uint32_t ph, pl;
                split2(v0, v1, ph, pl);
                *reinterpret_cast<uint32_t*>(&g_hh[base + c]) = ph;
                *reinterpret_cast<uint32_t*>(&g_hl[base + c]) = pl;
            }
        }
    }
}

// ---------------- GEMM2: Y = gate * (H @ W2 + b2), split-bf16 triple MMA ----------------
__global__ __launch_bounds__(NT, 2) void k_gemm2(const float* __restrict__ b2) {
    const int e   = blockIdx.z;
    const int cnt = g_cnt[e];
    const int mb  = blockIdx.y * BM;
    if (mb >= cnt) return;
    const int nb  = blockIdx.x * BN;

    __shared__ __nv_bfloat16 Ash[2][BM * LDAS];
    __shared__ __nv_bfloat16 Asl[2][BM * LDAS];
    __shared__ __nv_bfloat16 Bsh[2][BK * LDBS];
    __shared__ __nv_bfloat16 Bsl[2][BK * LDBS];

    const int tid = threadIdx.x;
    const int a_row = tid >> 1;
    const int a_col = (tid & 1) * 8;
    const int b_kr  = (tid & 127) >> 3;
    const int b_nc  = (tid & 7) * 8;
    // rows >= cnt read stale-but-finite scratch; their outputs are never stored
    const __nv_bfloat16* agh = g_hh + ((size_t)e * CAP + mb + a_row) * HH + a_col;
    const __nv_bfloat16* agl = g_hl + ((size_t)e * CAP + mb + a_row) * HH + a_col;
    const __nv_bfloat16* wbh = g_w2h + (size_t)e * HH * DD + (size_t)b_kr * DD + nb + b_nc;
    const __nv_bfloat16* wbl = g_w2l + (size_t)e * HH * DD + (size_t)b_kr * DD + nb + b_nc;

    const uint32_t sAh = (uint32_t)__cvta_generic_to_shared(&Ash[0][0]);
    const uint32_t sAl = (uint32_t)__cvta_generic_to_shared(&Asl[0][0]);
    const uint32_t sBh = (uint32_t)__cvta_generic_to_shared(&Bsh[0][0]);
    const uint32_t sBl = (uint32_t)__cvta_generic_to_shared(&Bsl[0][0]);
    const uint32_t aoff = (a_row * LDAS + a_col) * 2;
    const uint32_t boff = (b_kr * LDBS + b_nc) * 2;

    const int w = tid >> 5, lane = tid & 31;
    const int wm = (w >> 1) * 32, wn = (w & 1) * 32;
    const int g = lane >> 2, tq = lane & 3;
    const int lr = (lane & 7) + ((lane >> 3) & 1) * 8;
    const int lc = ((lane >> 4) & 1) * 8;
    const uint32_t aA0 = ((wm + lr) * LDAS + lc) * 2;
    const uint32_t aA1 = ((wm + 16 + lr) * LDAS + lc) * 2;
    const uint32_t bA0 = (lr * LDBS + wn + lc) * 2;
    const uint32_t bA1 = (lr * LDBS + wn + 16 + lc) * 2;

    float acc[2][4][4];
    #pragma unroll
    for (int a = 0; a < 2; a++)
        #pragma unroll
        for (int b = 0; b < 4; b++)
            #pragma unroll
            for (int c = 0; c < 4; c++) acc[a][b][c] = 0.f;

    const int NS = HH / BK;
    {
        cp16(sAh + aoff, agh);
        cp16(sAl + aoff, agl);
        if (tid < 128) cp16(sBh + boff, wbh);
        else           cp16(sBl + boff, wbl);
        CP_COMMIT();
    }
    for (int s = 0; s < NS; s++) {
        const int b = s & 1;
        if (s + 1 < NS) {
            const int kt = (s + 1) * BK;
            const uint32_t ao = (b ^ 1) * (BM * LDAS * 2) + aoff;
            const uint32_t bo = (b ^ 1) * (BK * LDBS * 2) + boff;
            cp16(sAh + ao, agh + kt);
            cp16(sAl + ao, agl + kt);
            if (tid < 128) cp16(sBh + bo, wbh + (size_t)kt * DD);
            else           cp16(sBl + bo, wbl + (size_t)kt * DD);
            CP_COMMIT();
            asm volatile("cp.async.wait_group 1;\n");
        } else {
            asm volatile("cp.async.wait_group 0;\n");
        }
        __syncthreads();

        uint32_t ah[2][4], al[2][4], bh[2][4], bl[2][4];
        const uint32_t Ab  = sAh + b * (BM * LDAS * 2);
        const uint32_t Alb = sAl + b * (BM * LDAS * 2);
        const uint32_t Bb  = sBh + b * (BK * LDBS * 2);
        const uint32_t Blb = sBl + b * (BK * LDBS * 2);
        ldsm_x4(ah[0], Ab + aA0);
        ldsm_x4(ah[1], Ab + aA1);
        ldsm_x4(al[0], Alb + aA0);
        ldsm_x4(al[1], Alb + aA1);
        ldsm_x4_t(bh[0], Bb + bA0);
        ldsm_x4_t(bh[1], Bb + bA1);
        ldsm_x4_t(bl[0], Blb + bA0);
        ldsm_x4_t(bl[1], Blb + bA1);

        #pragma unroll
        for (int mf = 0; mf < 2; mf++)
            #pragma unroll
            for (int nf = 0; nf < 4; nf++) {
                const uint32_t* bph = &bh[nf >> 1][(nf & 1) * 2];
                const uint32_t* bpl = &bl[nf >> 1][(nf & 1) * 2];
                mma_bf16(acc[mf][nf], ah[mf], bph);
                mma_bf16(acc[mf][nf], ah[mf], bpl);
                mma_bf16(acc[mf][nf], al[mf], bph);
            }
        __syncthreads();
    }

    // epilogue: +b2, * gate, store fp32 row into Y scratch
    #pragma unroll
    for (int mf = 0; mf < 2; mf++) {
        #pragma unroll
        for (int rr = 0; rr < 2; rr++) {
            int m = mb + wm + mf * 16 + g + rr * 8;
            if (m >= cnt) continue;
            float gate = g_gate[e * CAP + m];
            int   dst  = g_dst[e * CAP + m];
            float* yrow = g_y + (size_t)dst * DD + nb;
            #pragma unroll
            for (int nf = 0; nf < 4; nf++) {
                int c = wn + nf * 8 + 2 * tq;
                float2 pr;
                pr.x = (acc[mf][nf][rr * 2 + 0] + b2[e * DD + nb + c]) * gate;
                pr.y = (acc[mf][nf][rr * 2 + 1] + b2[e * DD + nb + c + 1]) * gate;
                *reinterpret_cast<float2*>(&yrow[c]) = pr;
            }
        }
    }
}

__global__ void k_combine(float* __restrict__ out) {
    int i = blockIdx.x * blockDim.x + threadIdx.x;
    int t = i >> 10;
    int d = i & (DD - 1);
    out[i] = g_y[(size_t)(2 * t) * DD + d] + g_y[(size_t)(2 * t + 1) * DD + d];
}

// ---------------- launch ----------------
extern "C" void kernel_launch(void* const* d_in, const int* in_sizes, int n_in,
                              void* d_out, int out_size) {
    const float* x  = (const float*)d_in[0];
    const float* Wr = (const float*)d_in[1];
    const float* br = (const float*)d_in[2];
    const float* W1 = (const float*)d_in[3];
    const float* b1 = (const float*)d_in[4];
    const float* W2 = (const float*)d_in[5];
    const float* b2 = (const float*)d_in[6];
    float* out = (float*)d_out;

    k_zero<<<1, 32>>>();
    k_cvt2<<<2048, 256>>>(x,  0, NTOK * DD / 4);
    k_cvt2<<<8192, 256>>>(W1, 1, EE * DD * HH / 4);
    k_cvt2<<<8192, 256>>>(W2, 2, EE * HH * DD / 4);
    k_router<<<NTOK, 256>>>(x, Wr, br);
    k_gemm1<<<dim3(HH / BN, CAP / BM, EE), NT>>>(b1);
    k_gemm2<<<dim3(DD / BN, CAP / BM, EE), NT>>>(b2);
    k_combine<<<(NTOK * DD) / 256, 256>>>(out);
}

// round 4
// speedup vs baseline: 4.5562x; 2.3143x over previous
#include <cuda_runtime.h>
#include <cuda_bf16.h>
#include <cuda_fp16.h>
#include <stdint.h>
#include <math.h>

// Problem constants
#define NTOK 4096        // B*T
#define DD   1024        // model dim
#define EE   8           // experts
#define HH   2048        // expert hidden
#define CAP  4096        // max tokens per expert

// GEMM tiling
#define BM 128
#define BN 128
#define BK 32
#define LDAS 40          // BK + 8 pad (fp16 elems); 80B rows -> conflict-free ldmatrix
#define LDBS 136         // BN + 8 pad; 272B rows -> conflict-free ldmatrix
#define NT 256

// ---------------- static scratch (no allocations allowed) ----------------
__device__ int   g_cnt[EE];
__device__ int   g_tok[EE * CAP];
__device__ float g_gate[EE * CAP];
__device__ int   g_dst[EE * CAP];
__device__ __half g_xf[(size_t)NTOK * DD];          // 8 MB
__device__ __half g_w1f[(size_t)EE * DD * HH];      // 32 MB
__device__ __half g_w2f[(size_t)EE * HH * DD];      // 32 MB
__device__ __half g_hf[(size_t)EE * CAP * HH];      // 128 MB
__device__ float g_y[(size_t)NTOK * 2 * DD];        // 32 MB

// ---------------- tiny kernels ----------------
__global__ void k_zero() {
    if (threadIdx.x < EE) g_cnt[threadIdx.x] = 0;
}

// fp32 -> fp16 conversion. which: 0=x, 1=W1, 2=W2
__global__ void k_cvt(const float* __restrict__ src, int which, int n4) {
    __half* dst = (which == 0) ? g_xf : (which == 1) ? g_w1f : g_w2f;
    int i = blockIdx.x * blockDim.x + threadIdx.x;
    int stride = gridDim.x * blockDim.x;
    for (; i < n4; i += stride) {
        float4 v = reinterpret_cast<const float4*>(src)[i];
        __half2 lo = __float22half2_rn(make_float2(v.x, v.y));
        __half2 hi = __float22half2_rn(make_float2(v.z, v.w));
        uint2 o;
        o.x = *reinterpret_cast<uint32_t*>(&lo);
        o.y = *reinterpret_cast<uint32_t*>(&hi);
        reinterpret_cast<uint2*>(dst)[i] = o;
    }
}

__global__ void k_router(const float* __restrict__ x, const float* __restrict__ Wr,
                         const float* __restrict__ br) {
    const int t = blockIdx.x;
    const int lane = threadIdx.x & 31, w = threadIdx.x >> 5;
    const float* xr = x + (size_t)t * DD;
    float s = 0.f;
    for (int d = lane; d < DD; d += 32) s = fmaf(xr[d], Wr[d * EE + w], s);
    #pragma unroll
    for (int o = 16; o; o >>= 1) s += __shfl_xor_sync(0xffffffffu, s, o);
    __shared__ float lg[EE];
    if (lane == 0) lg[w] = s + br[w];
    __syncthreads();
    if (threadIdx.x == 0) {
        float v0 = -3.4e38f; int i0 = 0;
        #pragma unroll
        for (int e = 0; e < EE; e++) if (lg[e] > v0) { v0 = lg[e]; i0 = e; }
        float v1 = -3.4e38f; int i1 = 0;
        #pragma unroll
        for (int e = 0; e < EE; e++) if (e != i0 && lg[e] > v1) { v1 = lg[e]; i1 = e; }
        float eb  = expf(v1 - v0);
        float inv = 1.f / (1.f + eb);
        float g0 = inv, g1 = eb * inv;
        int p0 = atomicAdd(&g_cnt[i0], 1);
        g_tok[i0 * CAP + p0] = t; g_gate[i0 * CAP + p0] = g0; g_dst[i0 * CAP + p0] = 2 * t;
        int p1 = atomicAdd(&g_cnt[i1], 1);
        g_tok[i1 * CAP + p1] = t; g_gate[i1 * CAP + p1] = g1; g_dst[i1 * CAP + p1] = 2 * t + 1;
    }
}

// ---------------- asm helpers ----------------
__device__ __forceinline__ void mma_f16(float c[4], const uint32_t a[4], const uint32_t b[2]) {
    asm volatile(
        "mma.sync.aligned.m16n8k16.row.col.f32.f16.f16.f32 "
        "{%0,%1,%2,%3}, {%4,%5,%6,%7}, {%8,%9}, {%0,%1,%2,%3};\n"
        : "+f"(c[0]), "+f"(c[1]), "+f"(c[2]), "+f"(c[3])
        : "r"(a[0]), "r"(a[1]), "r"(a[2]), "r"(a[3]), "r"(b[0]), "r"(b[1]));
}
__device__ __forceinline__ void ldsm_x4(uint32_t r[4], uint32_t addr) {
    asm volatile("ldmatrix.sync.aligned.m8n8.x4.shared.b16 {%0,%1,%2,%3}, [%4];\n"
        : "=r"(r[0]), "=r"(r[1]), "=r"(r[2]), "=r"(r[3]) : "r"(addr));
}
__device__ __forceinline__ void ldsm_x4_t(uint32_t r[4], uint32_t addr) {
    asm volatile("ldmatrix.sync.aligned.m8n8.x4.trans.shared.b16 {%0,%1,%2,%3}, [%4];\n"
        : "=r"(r[0]), "=r"(r[1]), "=r"(r[2]), "=r"(r[3]) : "r"(addr));
}
__device__ __forceinline__ void cp16(uint32_t dst, const void* src) {
    asm volatile("cp.async.cg.shared.global [%0], [%1], 16;\n" :: "r"(dst), "l"(src));
}
__device__ __forceinline__ void cp16z(uint32_t dst, const void* src, uint32_t sz) {
    asm volatile("cp.async.cg.shared.global [%0], [%1], 16, %2;\n" :: "r"(dst), "l"(src), "r"(sz));
}
#define CP_COMMIT() asm volatile("cp.async.commit_group;\n")

// ---------------- GEMM1: H = relu(Xg @ W1 + b1), fp16 MMA ----------------
__global__ __launch_bounds__(NT, 2) void k_gemm1(const float* __restrict__ b1) {
    const int e   = blockIdx.z;
    const int cnt = g_cnt[e];
    const int mb  = blockIdx.y * BM;
    if (mb >= cnt) return;
    const int nb  = blockIdx.x * BN;

    __shared__ __half Ash[2][BM * LDAS];
    __shared__ __half Bsh[2][BK * LDBS];
    __shared__ int stok[BM];

    const int tid = threadIdx.x;
    if (tid < BM) {
        int m = mb + tid;
        stok[tid] = (m < cnt) ? g_tok[e * CAP + m] : -1;
    }
    __syncthreads();

    // loader coords: A: 2 thr/row (2x16B each); B: 8 thr/row (2x16B each)
    const int a_row = tid >> 1;
    const int a_col = (tid & 1) * 16;
    const int b_kr  = tid >> 3;
    const int b_nc  = (tid & 7) * 16;
    const int atok  = stok[a_row];
    const uint32_t a_sz = (atok >= 0) ? 16u : 0u;
    const __half* agp = g_xf + (atok >= 0 ? (size_t)atok * DD + a_col : 0);
    const __half* wbp = g_w1f + (size_t)e * DD * HH + (size_t)b_kr * HH + nb + b_nc;

    const uint32_t sA = (uint32_t)__cvta_generic_to_shared(&Ash[0][0]);
    const uint32_t sB = (uint32_t)__cvta_generic_to_shared(&Bsh[0][0]);
    const uint32_t aoff = (a_row * LDAS + a_col) * 2;
    const uint32_t boff = (b_kr * LDBS + b_nc) * 2;

    // fragment coords: 8 warps as 2(m) x 4(n); warp tile 64x32
    const int w = tid >> 5, lane = tid & 31;
    const int wm = (w >> 2) * 64, wn = (w & 3) * 32;
    const int g = lane >> 2, tq = lane & 3;
    const int alr = lane & 15, ahc = (lane >> 4) * 8;
    uint32_t aoffs[4], boffs[2];
    #pragma unroll
    for (int mf = 0; mf < 4; mf++)
        aoffs[mf] = ((wm + mf * 16 + alr) * LDAS + ahc) * 2;
    #pragma unroll
    for (int ns = 0; ns < 2; ns++)
        boffs[ns] = (alr * LDBS + wn + ns * 16 + ahc) * 2;

    float acc[4][4][4];
    #pragma unroll
    for (int a = 0; a < 4; a++)
        #pragma unroll
        for (int b = 0; b < 4; b++)
            #pragma unroll
            for (int c = 0; c < 4; c++) acc[a][b][c] = 0.f;

    const int NS = DD / BK;
    // prefetch stage 0
    {
        cp16z(sA + aoff, agp, a_sz);
        cp16z(sA + aoff + 16, agp + 8, a_sz);
        cp16(sB + boff, wbp);
        cp16(sB + boff + 16, wbp + 8);
        CP_COMMIT();
    }
    for (int s = 0; s < NS; s++) {
        const int buf = s & 1;
        if (s + 1 < NS) {
            const int kt = (s + 1) * BK;
            const uint32_t ao = (buf ^ 1) * (BM * LDAS * 2) + aoff;
            const uint32_t bo = (buf ^ 1) * (BK * LDBS * 2) + boff;
            cp16z(sA + ao, agp + kt, a_sz);
            cp16z(sA + ao + 16, agp + kt + 8, a_sz);
            cp16(sB + bo, wbp + (size_t)kt * HH);
            cp16(sB + bo + 16, wbp + (size_t)kt * HH + 8);
            CP_COMMIT();
            asm volatile("cp.async.wait_group 1;\n");
        } else {
            asm volatile("cp.async.wait_group 0;\n");
        }
        __syncthreads();

        const uint32_t Ab = sA + buf * (BM * LDAS * 2);
        const uint32_t Bb = sB + buf * (BK * LDBS * 2);
        #pragma unroll
        for (int kk = 0; kk < BK; kk += 16) {
            uint32_t ah[4][4], bfr[2][4];
            #pragma unroll
            for (int mf = 0; mf < 4; mf++) ldsm_x4(ah[mf], Ab + aoffs[mf] + kk * 2);
            #pragma unroll
            for (int ns = 0; ns < 2; ns++) ldsm_x4_t(bfr[ns], Bb + boffs[ns] + kk * (LDBS * 2));
            #pragma unroll
            for (int mf = 0; mf < 4; mf++)
                #pragma unroll
                for (int nf = 0; nf < 4; nf++)
                    mma_f16(acc[mf][nf], ah[mf], &bfr[nf >> 1][(nf & 1) * 2]);
        }
        __syncthreads();
    }

    // epilogue: +b1, relu, store fp16 h
    #pragma unroll
    for (int mf = 0; mf < 4; mf++) {
        #pragma unroll
        for (int rr = 0; rr < 2; rr++) {
            int m = mb + wm + mf * 16 + g + rr * 8;
            if (m >= cnt) continue;
            size_t base = ((size_t)e * CAP + m) * HH + nb;
            #pragma unroll
            for (int nf = 0; nf < 4; nf++) {
                int c = wn + nf * 8 + 2 * tq;
                float v0 = fmaxf(acc[mf][nf][rr * 2 + 0] + b1[e * HH + nb + c], 0.f);
                float v1 = fmaxf(acc[mf][nf][rr * 2 + 1] + b1[e * HH + nb + c + 1], 0.f);
                __half2 pr = __float22half2_rn(make_float2(v0, v1));
                *reinterpret_cast<__half2*>(&g_hf[base + c]) = pr;
            }
        }
    }
}

// ---------------- GEMM2: Y = gate * (H @ W2 + b2), fp16 MMA ----------------
__global__ __launch_bounds__(NT, 2) void k_gemm2(const float* __restrict__ b2) {
    const int e   = blockIdx.z;
    const int cnt = g_cnt[e];
    const int mb  = blockIdx.y * BM;
    if (mb >= cnt) return;
    const int nb  = blockIdx.x * BN;

    __shared__ __half Ash[2][BM * LDAS];
    __shared__ __half Bsh[2][BK * LDBS];

    const int tid = threadIdx.x;
    const int a_row = tid >> 1;
    const int a_col = (tid & 1) * 16;
    const int b_kr  = tid >> 3;
    const int b_nc  = (tid & 7) * 16;
    // rows >= cnt read stale-but-finite scratch; their outputs are never stored
    const __half* agp = g_hf + ((size_t)e * CAP + mb + a_row) * HH + a_col;
    const __half* wbp = g_w2f + (size_t)e * HH * DD + (size_t)b_kr * DD + nb + b_nc;

    const uint32_t sA = (uint32_t)__cvta_generic_to_shared(&Ash[0][0]);
    const uint32_t sB = (uint32_t)__cvta_generic_to_shared(&Bsh[0][0]);
    const uint32_t aoff = (a_row * LDAS + a_col) * 2;
    const uint32_t boff = (b_kr * LDBS + b_nc) * 2;

    const int w = tid >> 5, lane = tid & 31;
    const int wm = (w >> 2) * 64, wn = (w & 3) * 32;
    const int g = lane >> 2, tq = lane & 3;
    const int alr = lane & 15, ahc = (lane >> 4) * 8;
    uint32_t aoffs[4], boffs[2];
    #pragma unroll
    for (int mf = 0; mf < 4; mf++)
        aoffs[mf] = ((wm + mf * 16 + alr) * LDAS + ahc) * 2;
    #pragma unroll
    for (int ns = 0; ns < 2; ns++)
        boffs[ns] = (alr * LDBS + wn + ns * 16 + ahc) * 2;

    float acc[4][4][4];
    #pragma unroll
    for (int a = 0; a < 4; a++)
        #pragma unroll
        for (int b = 0; b < 4; b++)
            #pragma unroll
            for (int c = 0; c < 4; c++) acc[a][b][c] = 0.f;

    const int NS = HH / BK;
    {
        cp16(sA + aoff, agp);
        cp16(sA + aoff + 16, agp + 8);
        cp16(sB + boff, wbp);
        cp16(sB + boff + 16, wbp + 8);
        CP_COMMIT();
    }
    for (int s = 0; s < NS; s++) {
        const int buf = s & 1;
        if (s + 1 < NS) {
            const int kt = (s + 1) * BK;
            const uint32_t ao = (buf ^ 1) * (BM * LDAS * 2) + aoff;
            const uint32_t bo = (buf ^ 1) * (BK * LDBS * 2) + boff;
            cp16(sA + ao, agp + kt);
            cp16(sA + ao + 16, agp + kt + 8);
            cp16(sB + bo, wbp + (size_t)kt * DD);
            cp16(sB + bo + 16, wbp + (size_t)kt * DD + 8);
            CP_COMMIT();
            asm volatile("cp.async.wait_group 1;\n");
        } else {
            asm volatile("cp.async.wait_group 0;\n");
        }
        __syncthreads();

        const uint32_t Ab = sA + buf * (BM * LDAS * 2);
        const uint32_t Bb = sB + buf * (BK * LDBS * 2);
        #pragma unroll
        for (int kk = 0; kk < BK; kk += 16) {
            uint32_t ah[4][4], bfr[2][4];
            #pragma unroll
            for (int mf = 0; mf < 4; mf++) ldsm_x4(ah[mf], Ab + aoffs[mf] + kk * 2);
            #pragma unroll
            for (int ns = 0; ns < 2; ns++) ldsm_x4_t(bfr[ns], Bb + boffs[ns] + kk * (LDBS * 2));
            #pragma unroll
            for (int mf = 0; mf < 4; mf++)
                #pragma unroll
                for (int nf = 0; nf < 4; nf++)
                    mma_f16(acc[mf][nf], ah[mf], &bfr[nf >> 1][(nf & 1) * 2]);
        }
        __syncthreads();
    }

    // epilogue: +b2, * gate, store fp32 row into Y scratch
    #pragma unroll
    for (int mf = 0; mf < 4; mf++) {
        #pragma unroll
        for (int rr = 0; rr < 2; rr++) {
            int m = mb + wm + mf * 16 + g + rr * 8;
            if (m >= cnt) continue;
            float gate = g_gate[e * CAP + m];
            int   dst  = g_dst[e * CAP + m];
            float* yrow = g_y + (size_t)dst * DD + nb;
            #pragma unroll
            for (int nf = 0; nf < 4; nf++) {
                int c = wn + nf * 8 + 2 * tq;
                float2 pr;
                pr.x = (acc[mf][nf][rr * 2 + 0] + b2[e * DD + nb + c]) * gate;
                pr.y = (acc[mf][nf][rr * 2 + 1] + b2[e * DD + nb + c + 1]) * gate;
                *reinterpret_cast<float2*>(&yrow[c]) = pr;
            }
        }
    }
}

__global__ void k_combine(float* __restrict__ out) {
    int i = blockIdx.x * blockDim.x + threadIdx.x;
    int t = i >> 10;
    int d = i & (DD - 1);
    out[i] = g_y[(size_t)(2 * t) * DD + d] + g_y[(size_t)(2 * t + 1) * DD + d];
}

// ---------------- launch ----------------
extern "C" void kernel_launch(void* const* d_in, const int* in_sizes, int n_in,
                              void* d_out, int out_size) {
    const float* x  = (const float*)d_in[0];
    const float* Wr = (const float*)d_in[1];
    const float* br = (const float*)d_in[2];
    const float* W1 = (const float*)d_in[3];
    const float* b1 = (const float*)d_in[4];
    const float* W2 = (const float*)d_in[5];
    const float* b2 = (const float*)d_in[6];
    float* out = (float*)d_out;

    k_zero<<<1, 32>>>();
    k_cvt<<<1024, 256>>>(x,  0, NTOK * DD / 4);
    k_cvt<<<4096, 256>>>(W1, 1, EE * DD * HH / 4);
    k_cvt<<<4096, 256>>>(W2, 2, EE * HH * DD / 4);
    k_router<<<NTOK, 256>>>(x, Wr, br);
    k_gemm1<<<dim3(HH / BN, CAP / BM, EE), NT>>>(b1);
    k_gemm2<<<dim3(DD / BN, CAP / BM, EE), NT>>>(b2);
    k_combine<<<(NTOK * DD) / 256, 256>>>(out);
}

// round 8
// speedup vs baseline: 4.9175x; 1.0793x over previous
#include <cuda_runtime.h>
#include <cuda_bf16.h>
#include <cuda_fp16.h>
#include <stdint.h>
#include <math.h>

// Problem constants
#define NTOK 4096
#define DD   1024
#define EE   8
#define HH   2048
#define CAP  4096

// GEMM tiling
#define BM 128
#define BN 128
#define BK 32
#define LDAS 40          // BK + 8 pad (fp16 elems); 80B rows
#define LDBS 136         // BN + 8 pad; 272B rows
#define NT 256
#define NSTG 4
#define ASTB (BM * LDAS * 2)   // 10240 B per A stage
#define BSTB (BK * LDBS * 2)   // 8704 B per B stage
#define SMEM_DYN (NSTG * (ASTB + BSTB))   // 75776 B

// ---------------- static scratch (no allocations allowed) ----------------
__device__ int   g_cnt[EE];
__device__ int   g_tok[EE * CAP];
__device__ float g_gate[EE * CAP];
__device__ int   g_dst[EE * CAP];
__device__ __half g_xf[(size_t)NTOK * DD];          // 8 MB
__device__ __half g_w1f[(size_t)EE * DD * HH];      // 32 MB
__device__ __half g_w2f[(size_t)EE * HH * DD];      // 32 MB
__device__ __half g_hf[(size_t)EE * CAP * HH];      // 128 MB
__device__ float g_y[(size_t)NTOK * 2 * DD];        // 32 MB

// ---------------- tiny kernels ----------------
__global__ void k_zero() {
    if (threadIdx.x < EE) g_cnt[threadIdx.x] = 0;
}

// fp32 -> fp16 conversion for weights. which: 1=W1, 2=W2
__global__ void k_cvt(const float* __restrict__ src, int which, int n4) {
    __half* dst = (which == 1) ? g_w1f : g_w2f;
    int i = blockIdx.x * blockDim.x + threadIdx.x;
    int stride = gridDim.x * blockDim.x;
    for (; i < n4; i += stride) {
        float4 v = reinterpret_cast<const float4*>(src)[i];
        __half2 lo = __float22half2_rn(make_float2(v.x, v.y));
        __half2 hi = __float22half2_rn(make_float2(v.z, v.w));
        uint2 o;
        o.x = *reinterpret_cast<uint32_t*>(&lo);
        o.y = *reinterpret_cast<uint32_t*>(&hi);
        reinterpret_cast<uint2*>(dst)[i] = o;
    }
}

// Router + fused x->fp16 conversion. One block (256 thr) per token.
__global__ void k_router(const float* __restrict__ x, const float* __restrict__ Wr,
                         const float* __restrict__ br) {
    const int t = blockIdx.x;
    const int lane = threadIdx.x & 31, w = threadIdx.x >> 5;
    const float* xr = x + (size_t)t * DD;
    float s = 0.f;
    for (int d = lane; d < DD; d += 32) s = fmaf(xr[d], Wr[d * EE + w], s);
    #pragma unroll
    for (int o = 16; o; o >>= 1) s += __shfl_xor_sync(0xffffffffu, s, o);
    __shared__ float lg[EE];
    if (lane == 0) lg[w] = s + br[w];
    // fused conversion: each thread converts 4 contiguous floats (L2-hot reread)
    {
        int i = threadIdx.x;
        float4 v = reinterpret_cast<const float4*>(xr)[i];
        __half2 lo = __float22half2_rn(make_float2(v.x, v.y));
        __half2 hi = __float22half2_rn(make_float2(v.z, v.w));
        uint2 o;
        o.x = *reinterpret_cast<uint32_t*>(&lo);
        o.y = *reinterpret_cast<uint32_t*>(&hi);
        reinterpret_cast<uint2*>(g_xf + (size_t)t * DD)[i] = o;
    }
    __syncthreads();
    if (threadIdx.x == 0) {
        float v0 = -3.4e38f; int i0 = 0;
        #pragma unroll
        for (int e = 0; e < EE; e++) if (lg[e] > v0) { v0 = lg[e]; i0 = e; }
        float v1 = -3.4e38f; int i1 = 0;
        #pragma unroll
        for (int e = 0; e < EE; e++) if (e != i0 && lg[e] > v1) { v1 = lg[e]; i1 = e; }
        float eb  = expf(v1 - v0);
        float inv = 1.f / (1.f + eb);
        float g0 = inv, g1 = eb * inv;
        int p0 = atomicAdd(&g_cnt[i0], 1);
        g_tok[i0 * CAP + p0] = t; g_gate[i0 * CAP + p0] = g0; g_dst[i0 * CAP + p0] = 2 * t;
        int p1 = atomicAdd(&g_cnt[i1], 1);
        g_tok[i1 * CAP + p1] = t; g_gate[i1 * CAP + p1] = g1; g_dst[i1 * CAP + p1] = 2 * t + 1;
    }
}

// ---------------- asm helpers ----------------
__device__ __forceinline__ void mma_f16(float c[4], const uint32_t a[4], const uint32_t b[2]) {
    asm volatile(
        "mma.sync.aligned.m16n8k16.row.col.f32.f16.f16.f32 "
        "{%0,%1,%2,%3}, {%4,%5,%6,%7}, {%8,%9}, {%0,%1,%2,%3};\n"
        : "+f"(c[0]), "+f"(c[1]), "+f"(c[2]), "+f"(c[3])
        : "r"(a[0]), "r"(a[1]), "r"(a[2]), "r"(a[3]), "r"(b[0]), "r"(b[1]));
}
__device__ __forceinline__ void ldsm_x4(uint32_t r[4], uint32_t addr) {
    asm volatile("ldmatrix.sync.aligned.m8n8.x4.shared.b16 {%0,%1,%2,%3}, [%4];\n"
        : "=r"(r[0]), "=r"(r[1]), "=r"(r[2]), "=r"(r[3]) : "r"(addr));
}
__device__ __forceinline__ void ldsm_x4_t(uint32_t r[4], uint32_t addr) {
    asm volatile("ldmatrix.sync.aligned.m8n8.x4.trans.shared.b16 {%0,%1,%2,%3}, [%4];\n"
        : "=r"(r[0]), "=r"(r[1]), "=r"(r[2]), "=r"(r[3]) : "r"(addr));
}
__device__ __forceinline__ void cp16(uint32_t dst, const void* src) {
    asm volatile("cp.async.cg.shared.global [%0], [%1], 16;\n" :: "r"(dst), "l"(src));
}
__device__ __forceinline__ void cp16z(uint32_t dst, const void* src, uint32_t sz) {
    asm volatile("cp.async.cg.shared.global [%0], [%1], 16, %2;\n" :: "r"(dst), "l"(src), "r"(sz));
}
#define CP_COMMIT() asm volatile("cp.async.commit_group;\n")
#define CP_WAIT2()  asm volatile("cp.async.wait_group 2;\n")

// ---------------- GEMM1: H = relu(Xg @ W1 + b1), fp16 MMA, 4-stage pipe ----------------
__global__ __launch_bounds__(NT, 2) void k_gemm1(const float* __restrict__ b1) {
    const int e   = blockIdx.z;
    const int cnt = g_cnt[e];
    const int mb  = blockIdx.y * BM;
    if (mb >= cnt) return;
    const int nb  = blockIdx.x * BN;

    extern __shared__ char dynsmem[];
    const uint32_t sA = (uint32_t)__cvta_generic_to_shared(dynsmem);
    const uint32_t sB = sA + NSTG * ASTB;
    __shared__ int stok[BM];

    const int tid = threadIdx.x;
    if (tid < BM) {
        int m = mb + tid;
        stok[tid] = (m < cnt) ? g_tok[e * CAP + m] : -1;
    }
    __syncthreads();

    // loader coords: A: 2 thr/row (2x16B each); B: 8 thr/row (2x16B each)
    const int a_row = tid >> 1;
    const int a_col = (tid & 1) * 16;
    const int b_kr  = tid >> 3;
    const int b_nc  = (tid & 7) * 16;
    const int atok  = stok[a_row];
    const uint32_t a_sz = (atok >= 0) ? 16u : 0u;
    const __half* agp = g_xf + (atok >= 0 ? (size_t)atok * DD + a_col : 0);
    const __half* wbp = g_w1f + (size_t)e * DD * HH + (size_t)b_kr * HH + nb + b_nc;
    const uint32_t aoff = (a_row * LDAS + a_col) * 2;
    const uint32_t boff = (b_kr * LDBS + b_nc) * 2;

    // fragment coords: 8 warps as 2(m) x 4(n); warp tile 64x32
    const int w = tid >> 5, lane = tid & 31;
    const int wm = (w >> 2) * 64, wn = (w & 3) * 32;
    const int g = lane >> 2, tq = lane & 3;
    const int alr = lane & 15, ahc = (lane >> 4) * 8;
    uint32_t aoffs[4], boffs[2];
    #pragma unroll
    for (int mf = 0; mf < 4; mf++)
        aoffs[mf] = ((wm + mf * 16 + alr) * LDAS + ahc) * 2;
    #pragma unroll
    for (int ns = 0; ns < 2; ns++)
        boffs[ns] = (alr * LDBS + wn + ns * 16 + ahc) * 2;

    float acc[4][4][4];
    #pragma unroll
    for (int a = 0; a < 4; a++)
        #pragma unroll
        for (int b = 0; b < 4; b++)
            #pragma unroll
            for (int c = 0; c < 4; c++) acc[a][b][c] = 0.f;

    const int NS = DD / BK;   // 32
    // prologue: stages 0..2
    #pragma unroll
    for (int p = 0; p < NSTG - 1; p++) {
        const int kt = p * BK;
        const uint32_t ao = p * ASTB + aoff, bo = p * BSTB + boff;
        cp16z(sA + ao, agp + kt, a_sz);
        cp16z(sA + ao + 16, agp + kt + 8, a_sz);
        cp16(sB + bo, wbp + (size_t)kt * HH);
        cp16(sB + bo + 16, wbp + (size_t)kt * HH + 8);
        CP_COMMIT();
    }
    for (int s = 0; s < NS; s++) {
        CP_WAIT2();
        __syncthreads();
        if (s + NSTG - 1 < NS) {
            const int p = s + NSTG - 1;
            const int kt = p * BK;
            const uint32_t ao = (p & 3) * ASTB + aoff, bo = (p & 3) * BSTB + boff;
            cp16z(sA + ao, agp + kt, a_sz);
            cp16z(sA + ao + 16, agp + kt + 8, a_sz);
            cp16(sB + bo, wbp + (size_t)kt * HH);
            cp16(sB + bo + 16, wbp + (size_t)kt * HH + 8);
        }
        CP_COMMIT();

        const uint32_t Ab = sA + (s & 3) * ASTB;
        const uint32_t Bb = sB + (s & 3) * BSTB;
        #pragma unroll
        for (int kk = 0; kk < BK; kk += 16) {
            uint32_t ah[4][4], bfr[2][4];
            #pragma unroll
            for (int mf = 0; mf < 4; mf++) ldsm_x4(ah[mf], Ab + aoffs[mf] + kk * 2);
            #pragma unroll
            for (int ns = 0; ns < 2; ns++) ldsm_x4_t(bfr[ns], Bb + boffs[ns] + kk * (LDBS * 2));
            #pragma unroll
            for (int mf = 0; mf < 4; mf++)
                #pragma unroll
                for (int nf = 0; nf < 4; nf++)
                    mma_f16(acc[mf][nf], ah[mf], &bfr[nf >> 1][(nf & 1) * 2]);
        }
    }

    // epilogue: +b1, relu, store fp16 h
    #pragma unroll
    for (int mf = 0; mf < 4; mf++) {
        #pragma unroll
        for (int rr = 0; rr < 2; rr++) {
            int m = mb + wm + mf * 16 + g + rr * 8;
            if (m >= cnt) continue;
            size_t base = ((size_t)e * CAP + m) * HH + nb;
            #pragma unroll
            for (int nf = 0; nf < 4; nf++) {
                int c = wn + nf * 8 + 2 * tq;
                float v0 = fmaxf(acc[mf][nf][rr * 2 + 0] + b1[e * HH + nb + c], 0.f);
                float v1 = fmaxf(acc[mf][nf][rr * 2 + 1] + b1[e * HH + nb + c + 1], 0.f);
                __half2 pr = __float22half2_rn(make_float2(v0, v1));
                *reinterpret_cast<__half2*>(&g_hf[base + c]) = pr;
            }
        }
    }
}

// ---------------- GEMM2: Y = gate * (H @ W2 + b2), fp16 MMA, 4-stage pipe ----------------
__global__ __launch_bounds__(NT, 2) void k_gemm2(const float* __restrict__ b2) {
    const int e   = blockIdx.z;
    const int cnt = g_cnt[e];
    const int mb  = blockIdx.y * BM;
    if (mb >= cnt) return;
    const int nb  = blockIdx.x * BN;

    extern __shared__ char dynsmem[];
    const uint32_t sA = (uint32_t)__cvta_generic_to_shared(dynsmem);
    const uint32_t sB = sA + NSTG * ASTB;

    const int tid = threadIdx.x;
    const int a_row = tid >> 1;
    const int a_col = (tid & 1) * 16;
    const int b_kr  = tid >> 3;
    const int b_nc  = (tid & 7) * 16;
    // rows >= cnt read stale-but-finite scratch; their outputs are never stored
    const __half* agp = g_hf + ((size_t)e * CAP + mb + a_row) * HH + a_col;
    const __half* wbp = g_w2f + (size_t)e * HH * DD + (size_t)b_kr * DD + nb + b_nc;
    const uint32_t aoff = (a_row * LDAS + a_col) * 2;
    const uint32_t boff = (b_kr * LDBS + b_nc) * 2;

    const int w = tid >> 5, lane = tid & 31;
    const int wm = (w >> 2) * 64, wn = (w & 3) * 32;
    const int g = lane >> 2, tq = lane & 3;
    const int alr = lane & 15, ahc = (lane >> 4) * 8;
    uint32_t aoffs[4], boffs[2];
    #pragma unroll
    for (int mf = 0; mf < 4; mf++)
        aoffs[mf] = ((wm + mf * 16 + alr) * LDAS + ahc) * 2;
    #pragma unroll
    for (int ns = 0; ns < 2; ns++)
        boffs[ns] = (alr * LDBS + wn + ns * 16 + ahc) * 2;

    float acc[4][4][4];
    #pragma unroll
    for (int a = 0; a < 4; a++)
        #pragma unroll
        for (int b = 0; b < 4; b++)
            #pragma unroll
            for (int c = 0; c < 4; c++) acc[a][b][c] = 0.f;

    const int NS = HH / BK;   // 64
    #pragma unroll
    for (int p = 0; p < NSTG - 1; p++) {
        const int kt = p * BK;
        const uint32_t ao = p * ASTB + aoff, bo = p * BSTB + boff;
        cp16(sA + ao, agp + kt);
        cp16(sA + ao + 16, agp + kt + 8);
        cp16(sB + bo, wbp + (size_t)kt * DD);
        cp16(sB + bo + 16, wbp + (size_t)kt * DD + 8);
        CP_COMMIT();
    }
    for (int s = 0; s < NS; s++) {
        CP_WAIT2();
        __syncthreads();
        if (s + NSTG - 1 < NS) {
            const int p = s + NSTG - 1;
            const int kt = p * BK;
            const uint32_t ao = (p & 3) * ASTB + aoff, bo = (p & 3) * BSTB + boff;
            cp16(sA + ao, agp + kt);
            cp16(sA + ao + 16, agp + kt + 8);
            cp16(sB + bo, wbp + (size_t)kt * DD);
            cp16(sB + bo + 16, wbp + (size_t)kt * DD + 8);
        }
        CP_COMMIT();

        const uint32_t Ab = sA + (s & 3) * ASTB;
        const uint32_t Bb = sB + (s & 3) * BSTB;
        #pragma unroll
        for (int kk = 0; kk < BK; kk += 16) {
            uint32_t ah[4][4], bfr[2][4];
            #pragma unroll
            for (int mf = 0; mf < 4; mf++) ldsm_x4(ah[mf], Ab + aoffs[mf] + kk * 2);
            #pragma unroll
            for (int ns = 0; ns < 2; ns++) ldsm_x4_t(bfr[ns], Bb + boffs[ns] + kk * (LDBS * 2));
            #pragma unroll
            for (int mf = 0; mf < 4; mf++)
                #pragma unroll
                for (int nf = 0; nf < 4; nf++)
                    mma_f16(acc[mf][nf], ah[mf], &bfr[nf >> 1][(nf & 1) * 2]);
        }
    }

    // epilogue: +b2, * gate, store fp32 row into Y scratch
    #pragma unroll
    for (int mf = 0; mf < 4; mf++) {
        #pragma unroll
        for (int rr = 0; rr < 2; rr++) {
            int m = mb + wm + mf * 16 + g + rr * 8;
            if (m >= cnt) continue;
            float gate = g_gate[e * CAP + m];
            int   dst  = g_dst[e * CAP + m];
            float* yrow = g_y + (size_t)dst * DD + nb;
            #pragma unroll
            for (int nf = 0; nf < 4; nf++) {
                int c = wn + nf * 8 + 2 * tq;
                float2 pr;
                pr.x = (acc[mf][nf][rr * 2 + 0] + b2[e * DD + nb + c]) * gate;
                pr.y = (acc[mf][nf][rr * 2 + 1] + b2[e * DD + nb + c + 1]) * gate;
                *reinterpret_cast<float2*>(&yrow[c]) = pr;
            }
        }
    }
}

__global__ void k_combine(float* __restrict__ out) {
    int i = blockIdx.x * blockDim.x + threadIdx.x;
    int t = i >> 10;
    int d = i & (DD - 1);
    out[i] = g_y[(size_t)(2 * t) * DD + d] + g_y[(size_t)(2 * t + 1) * DD + d];
}

// ---------------- launch ----------------
extern "C" void kernel_launch(void* const* d_in, const int* in_sizes, int n_in,
                              void* d_out, int out_size) {
    const float* x  = (const float*)d_in[0];
    const float* Wr = (const float*)d_in[1];
    const float* br = (const float*)d_in[2];
    const float* W1 = (const float*)d_in[3];
    const float* b1 = (const float*)d_in[4];
    const float* W2 = (const float*)d_in[5];
    const float* b2 = (const float*)d_in[6];
    float* out = (float*)d_out;

    cudaFuncSetAttribute(k_gemm1, cudaFuncAttributeMaxDynamicSharedMemorySize, SMEM_DYN);
    cudaFuncSetAttribute(k_gemm2, cudaFuncAttributeMaxDynamicSharedMemorySize, SMEM_DYN);

    k_zero<<<1, 32>>>();
    k_cvt<<<4096, 256>>>(W1, 1, EE * DD * HH / 4);
    k_cvt<<<4096, 256>>>(W2, 2, EE * HH * DD / 4);
    k_router<<<NTOK, 256>>>(x, Wr, br);
    k_gemm1<<<dim3(HH / BN, CAP / BM, EE), NT, SMEM_DYN>>>(b1);
    k_gemm2<<<dim3(DD / BN, CAP / BM, EE), NT, SMEM_DYN>>>(b2);
    k_combine<<<(NTOK * DD) / 256, 256>>>(out);
}

// round 9
// speedup vs baseline: 4.9488x; 1.0064x over previous
#include <cuda_runtime.h>
#include <cuda_bf16.h>
#include <cuda_fp16.h>
#include <stdint.h>
#include <math.h>

// Problem constants
#define NTOK 4096
#define DD   1024
#define EE   8
#define HH   2048
#define CAP  4096

// GEMM tiling
#define BM 128
#define BN 128
#define BK 32
#define LDAS 40          // BK + 8 pad (fp16 elems); 80B rows
#define LDBS 136         // BN + 8 pad; 272B rows
#define NT 256
#define NSTG 4
#define ASTB (BM * LDAS * 2)   // 10240 B per A stage
#define BSTB (BK * LDBS * 2)   // 8704 B per B stage
#define SMEM_DYN (NSTG * (ASTB + BSTB))   // 75776 B

// ---------------- static scratch (no allocations allowed) ----------------
__device__ int   g_cnt[EE];
__device__ int   g_tok[EE * CAP];
__device__ float g_gate[EE * CAP];
__device__ __half g_xf[(size_t)NTOK * DD];          // 8 MB
__device__ __half g_w1f[(size_t)EE * DD * HH];      // 32 MB
__device__ __half g_w2f[(size_t)EE * HH * DD];      // 32 MB
__device__ __half g_hf[(size_t)EE * CAP * HH];      // 128 MB

// ---------------- tiny kernels ----------------
// Zero output (graph replays must not accumulate) + expert counters.
__global__ void k_zout(float* __restrict__ out) {
    int i = blockIdx.x * blockDim.x + threadIdx.x;
    reinterpret_cast<float4*>(out)[i] = make_float4(0.f, 0.f, 0.f, 0.f);
    if (blockIdx.x == 0 && threadIdx.x < EE) g_cnt[threadIdx.x] = 0;
}

// fp32 -> fp16 conversion for weights. which: 1=W1, 2=W2
__global__ void k_cvt(const float* __restrict__ src, int which, int n4) {
    __half* dst = (which == 1) ? g_w1f : g_w2f;
    int i = blockIdx.x * blockDim.x + threadIdx.x;
    int stride = gridDim.x * blockDim.x;
    for (; i < n4; i += stride) {
        float4 v = reinterpret_cast<const float4*>(src)[i];
        __half2 lo = __float22half2_rn(make_float2(v.x, v.y));
        __half2 hi = __float22half2_rn(make_float2(v.z, v.w));
        uint2 o;
        o.x = *reinterpret_cast<uint32_t*>(&lo);
        o.y = *reinterpret_cast<uint32_t*>(&hi);
        reinterpret_cast<uint2*>(dst)[i] = o;
    }
}

// Router: one WARP per token. Single pass over x: all-8-expert FMAs + fp16 convert.
__global__ void k_router(const float* __restrict__ x, const float* __restrict__ Wr,
                         const float* __restrict__ br) {
    const int t = blockIdx.x * 8 + (threadIdx.x >> 5);
    const int lane = threadIdx.x & 31;
    const float4* xr = reinterpret_cast<const float4*>(x + (size_t)t * DD);
    uint2* xo = reinterpret_cast<uint2*>(g_xf + (size_t)t * DD);

    float acc[EE];
    #pragma unroll
    for (int e = 0; e < EE; e++) acc[e] = 0.f;

    #pragma unroll
    for (int i = 0; i < 8; i++) {
        const int c = lane + i * 32;            // float4 index within row
        float4 v = xr[c];
        // fused fp16 conversion (coalesced 8B per lane)
        __half2 lo = __float22half2_rn(make_float2(v.x, v.y));
        __half2 hi = __float22half2_rn(make_float2(v.z, v.w));
        uint2 o;
        o.x = *reinterpret_cast<uint32_t*>(&lo);
        o.y = *reinterpret_cast<uint32_t*>(&hi);
        xo[c] = o;
        // logits: 8 experts per element, Wr row-major [D][E], L1-resident
        const float xv[4] = {v.x, v.y, v.z, v.w};
        #pragma unroll
        for (int j = 0; j < 4; j++) {
            const float4 w0 = *reinterpret_cast<const float4*>(Wr + (size_t)(c * 4 + j) * EE);
            const float4 w1 = *reinterpret_cast<const float4*>(Wr + (size_t)(c * 4 + j) * EE + 4);
            acc[0] = fmaf(xv[j], w0.x, acc[0]);
            acc[1] = fmaf(xv[j], w0.y, acc[1]);
            acc[2] = fmaf(xv[j], w0.z, acc[2]);
            acc[3] = fmaf(xv[j], w0.w, acc[3]);
            acc[4] = fmaf(xv[j], w1.x, acc[4]);
            acc[5] = fmaf(xv[j], w1.y, acc[5]);
            acc[6] = fmaf(xv[j], w1.z, acc[6]);
            acc[7] = fmaf(xv[j], w1.w, acc[7]);
        }
    }
    #pragma unroll
    for (int off = 16; off; off >>= 1)
        #pragma unroll
        for (int e = 0; e < EE; e++)
            acc[e] += __shfl_xor_sync(0xffffffffu, acc[e], off);

    if (lane == 0) {
        #pragma unroll
        for (int e = 0; e < EE; e++) acc[e] += br[e];
        float v0 = -3.4e38f; int i0 = 0;
        #pragma unroll
        for (int e = 0; e < EE; e++) if (acc[e] > v0) { v0 = acc[e]; i0 = e; }
        float v1 = -3.4e38f; int i1 = 0;
        #pragma unroll
        for (int e = 0; e < EE; e++) if (e != i0 && acc[e] > v1) { v1 = acc[e]; i1 = e; }
        float eb  = expf(v1 - v0);
        float inv = 1.f / (1.f + eb);
        int p0 = atomicAdd(&g_cnt[i0], 1);
        g_tok[i0 * CAP + p0] = t; g_gate[i0 * CAP + p0] = inv;
        int p1 = atomicAdd(&g_cnt[i1], 1);
        g_tok[i1 * CAP + p1] = t; g_gate[i1 * CAP + p1] = eb * inv;
    }
}

// ---------------- asm helpers ----------------
__device__ __forceinline__ void mma_f16(float c[4], const uint32_t a[4], const uint32_t b[2]) {
    asm volatile(
        "mma.sync.aligned.m16n8k16.row.col.f32.f16.f16.f32 "
        "{%0,%1,%2,%3}, {%4,%5,%6,%7}, {%8,%9}, {%0,%1,%2,%3};\n"
        : "+f"(c[0]), "+f"(c[1]), "+f"(c[2]), "+f"(c[3])
        : "r"(a[0]), "r"(a[1]), "r"(a[2]), "r"(a[3]), "r"(b[0]), "r"(b[1]));
}
__device__ __forceinline__ void ldsm_x4(uint32_t r[4], uint32_t addr) {
    asm volatile("ldmatrix.sync.aligned.m8n8.x4.shared.b16 {%0,%1,%2,%3}, [%4];\n"
        : "=r"(r[0]), "=r"(r[1]), "=r"(r[2]), "=r"(r[3]) : "r"(addr));
}
__device__ __forceinline__ void ldsm_x4_t(uint32_t r[4], uint32_t addr) {
    asm volatile("ldmatrix.sync.aligned.m8n8.x4.trans.shared.b16 {%0,%1,%2,%3}, [%4];\n"
        : "=r"(r[0]), "=r"(r[1]), "=r"(r[2]), "=r"(r[3]) : "r"(addr));
}
__device__ __forceinline__ void cp16(uint32_t dst, const void* src) {
    asm volatile("cp.async.cg.shared.global [%0], [%1], 16;\n" :: "r"(dst), "l"(src));
}
__device__ __forceinline__ void cp16z(uint32_t dst, const void* src, uint32_t sz) {
    asm volatile("cp.async.cg.shared.global [%0], [%1], 16, %2;\n" :: "r"(dst), "l"(src), "r"(sz));
}
#define CP_COMMIT() asm volatile("cp.async.commit_group;\n")
#define CP_WAIT2()  asm volatile("cp.async.wait_group 2;\n")

// ---------------- GEMM1: H = relu(Xg @ W1 + b1), fp16 MMA, 4-stage pipe ----------------
__global__ __launch_bounds__(NT, 2) void k_gemm1(const float* __restrict__ b1) {
    const int e   = blockIdx.z;
    const int cnt = g_cnt[e];
    const int mb  = blockIdx.y * BM;
    if (mb >= cnt) return;
    const int nb  = blockIdx.x * BN;

    extern __shared__ char dynsmem[];
    const uint32_t sA = (uint32_t)__cvta_generic_to_shared(dynsmem);
    const uint32_t sB = sA + NSTG * ASTB;
    __shared__ int stok[BM];

    const int tid = threadIdx.x;
    if (tid < BM) {
        int m = mb + tid;
        stok[tid] = (m < cnt) ? g_tok[e * CAP + m] : -1;
    }
    __syncthreads();

    const int a_row = tid >> 1;
    const int a_col = (tid & 1) * 16;
    const int b_kr  = tid >> 3;
    const int b_nc  = (tid & 7) * 16;
    const int atok  = stok[a_row];
    const uint32_t a_sz = (atok >= 0) ? 16u : 0u;
    const __half* agp = g_xf + (atok >= 0 ? (size_t)atok * DD + a_col : 0);
    const __half* wbp = g_w1f + (size_t)e * DD * HH + (size_t)b_kr * HH + nb + b_nc;
    const uint32_t aoff = (a_row * LDAS + a_col) * 2;
    const uint32_t boff = (b_kr * LDBS + b_nc) * 2;

    const int w = tid >> 5, lane = tid & 31;
    const int wm = (w >> 2) * 64, wn = (w & 3) * 32;
    const int g = lane >> 2, tq = lane & 3;
    const int alr = lane & 15, ahc = (lane >> 4) * 8;
    uint32_t aoffs[4], boffs[2];
    #pragma unroll
    for (int mf = 0; mf < 4; mf++)
        aoffs[mf] = ((wm + mf * 16 + alr) * LDAS + ahc) * 2;
    #pragma unroll
    for (int ns = 0; ns < 2; ns++)
        boffs[ns] = (alr * LDBS + wn + ns * 16 + ahc) * 2;

    float acc[4][4][4];
    #pragma unroll
    for (int a = 0; a < 4; a++)
        #pragma unroll
        for (int b = 0; b < 4; b++)
            #pragma unroll
            for (int c = 0; c < 4; c++) acc[a][b][c] = 0.f;

    const int NS = DD / BK;   // 32
    #pragma unroll
    for (int p = 0; p < NSTG - 1; p++) {
        const int kt = p * BK;
        const uint32_t ao = p * ASTB + aoff, bo = p * BSTB + boff;
        cp16z(sA + ao, agp + kt, a_sz);
        cp16z(sA + ao + 16, agp + kt + 8, a_sz);
        cp16(sB + bo, wbp + (size_t)kt * HH);
        cp16(sB + bo + 16, wbp + (size_t)kt * HH + 8);
        CP_COMMIT();
    }
    for (int s = 0; s < NS; s++) {
        CP_WAIT2();
        __syncthreads();
        if (s + NSTG - 1 < NS) {
            const int p = s + NSTG - 1;
            const int kt = p * BK;
            const uint32_t ao = (p & 3) * ASTB + aoff, bo = (p & 3) * BSTB + boff;
            cp16z(sA + ao, agp + kt, a_sz);
            cp16z(sA + ao + 16, agp + kt + 8, a_sz);
            cp16(sB + bo, wbp + (size_t)kt * HH);
            cp16(sB + bo + 16, wbp + (size_t)kt * HH + 8);
        }
        CP_COMMIT();

        const uint32_t Ab = sA + (s & 3) * ASTB;
        const uint32_t Bb = sB + (s & 3) * BSTB;
        #pragma unroll
        for (int kk = 0; kk < BK; kk += 16) {
            uint32_t ah[4][4], bfr[2][4];
            #pragma unroll
            for (int mf = 0; mf < 4; mf++) ldsm_x4(ah[mf], Ab + aoffs[mf] + kk * 2);
            #pragma unroll
            for (int ns = 0; ns < 2; ns++) ldsm_x4_t(bfr[ns], Bb + boffs[ns] + kk * (LDBS * 2));
            #pragma unroll
            for (int mf = 0; mf < 4; mf++)
                #pragma unroll
                for (int nf = 0; nf < 4; nf++)
                    mma_f16(acc[mf][nf], ah[mf], &bfr[nf >> 1][(nf & 1) * 2]);
        }
    }

    // epilogue: +b1, relu, store fp16 h
    #pragma unroll
    for (int mf = 0; mf < 4; mf++) {
        #pragma unroll
        for (int rr = 0; rr < 2; rr++) {
            int m = mb + wm + mf * 16 + g + rr * 8;
            if (m >= cnt) continue;
            size_t base = ((size_t)e * CAP + m) * HH + nb;
            #pragma unroll
            for (int nf = 0; nf < 4; nf++) {
                int c = wn + nf * 8 + 2 * tq;
                float v0 = fmaxf(acc[mf][nf][rr * 2 + 0] + b1[e * HH + nb + c], 0.f);
                float v1 = fmaxf(acc[mf][nf][rr * 2 + 1] + b1[e * HH + nb + c + 1], 0.f);
                __half2 pr = __float22half2_rn(make_float2(v0, v1));
                *reinterpret_cast<__half2*>(&g_hf[base + c]) = pr;
            }
        }
    }
}

// ---------------- GEMM2: out += gate * (H @ W2 + b2), fp16 MMA, atomic epilogue ----------------
__global__ __launch_bounds__(NT, 2) void k_gemm2(const float* __restrict__ b2,
                                                 float* __restrict__ out) {
    const int e   = blockIdx.z;
    const int cnt = g_cnt[e];
    const int mb  = blockIdx.y * BM;
    if (mb >= cnt) return;
    const int nb  = blockIdx.x * BN;

    extern __shared__ char dynsmem[];
    const uint32_t sA = (uint32_t)__cvta_generic_to_shared(dynsmem);
    const uint32_t sB = sA + NSTG * ASTB;

    const int tid = threadIdx.x;
    const int a_row = tid >> 1;
    const int a_col = (tid & 1) * 16;
    const int b_kr  = tid >> 3;
    const int b_nc  = (tid & 7) * 16;
    // rows >= cnt read stale-but-finite scratch; their outputs are never stored
    const __half* agp = g_hf + ((size_t)e * CAP + mb + a_row) * HH + a_col;
    const __half* wbp = g_w2f + (size_t)e * HH * DD + (size_t)b_kr * DD + nb + b_nc;
    const uint32_t aoff = (a_row * LDAS + a_col) * 2;
    const uint32_t boff = (b_kr * LDBS + b_nc) * 2;

    const int w = tid >> 5, lane = tid & 31;
    const int wm = (w >> 2) * 64, wn = (w & 3) * 32;
    const int g = lane >> 2, tq = lane & 3;
    const int alr = lane & 15, ahc = (lane >> 4) * 8;
    uint32_t aoffs[4], boffs[2];
    #pragma unroll
    for (int mf = 0; mf < 4; mf++)
        aoffs[mf] = ((wm + mf * 16 + alr) * LDAS + ahc) * 2;
    #pragma unroll
    for (int ns = 0; ns < 2; ns++)
        boffs[ns] = (alr * LDBS + wn + ns * 16 + ahc) * 2;

    float acc[4][4][4];
    #pragma unroll
    for (int a = 0; a < 4; a++)
        #pragma unroll
        for (int b = 0; b < 4; b++)
            #pragma unroll
            for (int c = 0; c < 4; c++) acc[a][b][c] = 0.f;

    const int NS = HH / BK;   // 64
    #pragma unroll
    for (int p = 0; p < NSTG - 1; p++) {
        const int kt = p * BK;
        const uint32_t ao = p * ASTB + aoff, bo = p * BSTB + boff;
        cp16(sA + ao, agp + kt);
        cp16(sA + ao + 16, agp + kt + 8);
        cp16(sB + bo, wbp + (size_t)kt * DD);
        cp16(sB + bo + 16, wbp + (size_t)kt * DD + 8);
        CP_COMMIT();
    }
    for (int s = 0; s < NS; s++) {
        CP_WAIT2();
        __syncthreads();
        if (s + NSTG - 1 < NS) {
            const int p = s + NSTG - 1;
            const int kt = p * BK;
            const uint32_t ao = (p & 3) * ASTB + aoff, bo = (p & 3) * BSTB + boff;
            cp16(sA + ao, agp + kt);
            cp16(sA + ao + 16, agp + kt + 8);
            cp16(sB + bo, wbp + (size_t)kt * DD);
            cp16(sB + bo + 16, wbp + (size_t)kt * DD + 8);
        }
        CP_COMMIT();

        const uint32_t Ab = sA + (s & 3) * ASTB;
        const uint32_t Bb = sB + (s & 3) * BSTB;
        #pragma unroll
        for (int kk = 0; kk < BK; kk += 16) {
            uint32_t ah[4][4], bfr[2][4];
            #pragma unroll
            for (int mf = 0; mf < 4; mf++) ldsm_x4(ah[mf], Ab + aoffs[mf] + kk * 2);
            #pragma unroll
            for (int ns = 0; ns < 2; ns++) ldsm_x4_t(bfr[ns], Bb + boffs[ns] + kk * (LDBS * 2));
            #pragma unroll
            for (int mf = 0; mf < 4; mf++)
                #pragma unroll
                for (int nf = 0; nf < 4; nf++)
                    mma_f16(acc[mf][nf], ah[mf], &bfr[nf >> 1][(nf & 1) * 2]);
        }
    }

    // epilogue: +b2, * gate, atomicAdd into out (2 expert contributions per token)
    #pragma unroll
    for (int mf = 0; mf < 4; mf++) {
        #pragma unroll
        for (int rr = 0; rr < 2; rr++) {
            int m = mb + wm + mf * 16 + g + rr * 8;
            if (m >= cnt) continue;
            float gate = g_gate[e * CAP + m];
            int   tokid = g_tok[e * CAP + m];
            float* orow = out + (size_t)tokid * DD + nb;
            #pragma unroll
            for (int nf = 0; nf < 4; nf++) {
                int c = wn + nf * 8 + 2 * tq;
                atomicAdd(&orow[c],     (acc[mf][nf][rr * 2 + 0] + b2[e * DD + nb + c]) * gate);
                atomicAdd(&orow[c + 1], (acc[mf][nf][rr * 2 + 1] + b2[e * DD + nb + c + 1]) * gate);
            }
        }
    }
}

// ---------------- launch ----------------
extern "C" void kernel_launch(void* const* d_in, const int* in_sizes, int n_in,
                              void* d_out, int out_size) {
    const float* x  = (const float*)d_in[0];
    const float* Wr = (const float*)d_in[1];
    const float* br = (const float*)d_in[2];
    const float* W1 = (const float*)d_in[3];
    const float* b1 = (const float*)d_in[4];
    const float* W2 = (const float*)d_in[5];
    const float* b2 = (const float*)d_in[6];
    float* out = (float*)d_out;

    cudaFuncSetAttribute(k_gemm1, cudaFuncAttributeMaxDynamicSharedMemorySize, SMEM_DYN);
    cudaFuncSetAttribute(k_gemm2, cudaFuncAttributeMaxDynamicSharedMemorySize, SMEM_DYN);

    k_zout<<<(NTOK * DD / 4) / 256, 256>>>(out);            // 1
    k_cvt<<<4096, 256>>>(W1, 1, EE * DD * HH / 4);          // 2
    k_cvt<<<4096, 256>>>(W2, 2, EE * HH * DD / 4);          // 3
    k_router<<<NTOK / 8, 256>>>(x, Wr, br);                 // 4
    k_gemm1<<<dim3(HH / BN, CAP / BM, EE), NT, SMEM_DYN>>>(b1);        // 5
    k_gemm2<<<dim3(DD / BN, CAP / BM, EE), NT, SMEM_DYN>>>(b2, out);   // 6  (ncu -s 5 lands here)
}

// round 10
// speedup vs baseline: 5.3995x; 1.0911x over previous
#include <cuda_runtime.h>
#include <cuda_bf16.h>
#include <cuda_fp16.h>
#include <stdint.h>
#include <math.h>

// Problem constants
#define NTOK 4096
#define DD   1024
#define EE   8
#define HH   2048
#define CAP  4096

// GEMM tiling
#define BM 128
#define BN 128
#define BK 32
#define LDAS 40          // BK + 8 pad (fp16 elems); 80B rows
#define LDBS 136         // BN + 8 pad; 272B rows
#define NT 256
#define NSTG 4
#define ASTB (BM * LDAS * 2)   // 10240 B per A stage
#define BSTB (BK * LDBS * 2)   // 8704 B per B stage
#define SMEM_DYN (NSTG * (ASTB + BSTB))   // 75776 B

// Router
#define RTB 512                 // threads per router block (16 warps = 16 tokens)
#define WRD (DD + 4)            // padded smem row stride for wrt[e][*]

// ---------------- static scratch (no allocations allowed) ----------------
__device__ int   g_cnt[EE];
__device__ int   g_tok[EE * CAP];
__device__ float g_gate[EE * CAP];
__device__ __half g_xf[(size_t)NTOK * DD];          // 8 MB
__device__ __half g_w1f[(size_t)EE * DD * HH];      // 32 MB
__device__ __half g_w2f[(size_t)EE * HH * DD];      // 32 MB
__device__ __half g_hf[(size_t)EE * CAP * HH];      // 128 MB

// ---------------- tiny kernels ----------------
// Zero output (graph replays must not accumulate) + expert counters.
__global__ void k_zout(float* __restrict__ out) {
    int i = blockIdx.x * blockDim.x + threadIdx.x;
    reinterpret_cast<float4*>(out)[i] = make_float4(0.f, 0.f, 0.f, 0.f);
    if (blockIdx.x == 0 && threadIdx.x < EE) g_cnt[threadIdx.x] = 0;
}

// fp32 -> fp16 conversion for weights. which: 1=W1, 2=W2
__global__ void k_cvt(const float* __restrict__ src, int which, int n4) {
    __half* dst = (which == 1) ? g_w1f : g_w2f;
    int i = blockIdx.x * blockDim.x + threadIdx.x;
    int stride = gridDim.x * blockDim.x;
    for (; i < n4; i += stride) {
        float4 v = reinterpret_cast<const float4*>(src)[i];
        __half2 lo = __float22half2_rn(make_float2(v.x, v.y));
        __half2 hi = __float22half2_rn(make_float2(v.z, v.w));
        uint2 o;
        o.x = *reinterpret_cast<uint32_t*>(&lo);
        o.y = *reinterpret_cast<uint32_t*>(&hi);
        reinterpret_cast<uint2*>(dst)[i] = o;
    }
}

// Router: warp per token; Wr staged transposed in smem (conflict-free LDS.128).
// Single coalesced pass over x does fp16 convert + all-8-expert logits.
__global__ __launch_bounds__(RTB) void k_router(const float* __restrict__ x,
                                                const float* __restrict__ Wr,
                                                const float* __restrict__ br) {
    __shared__ float wrt[EE * WRD];     // wrt[e*WRD + d] = Wr[d][e]
    const int tid = threadIdx.x;

    // stage + transpose Wr (one-time, 2048 float4 reads per block, L2-hot)
    for (int idx = tid; idx < DD * EE / 4; idx += RTB) {
        float4 v = reinterpret_cast<const float4*>(Wr)[idx];
        int d = idx >> 1, eb = (idx & 1) * 4;
        wrt[(eb + 0) * WRD + d] = v.x;
        wrt[(eb + 1) * WRD + d] = v.y;
        wrt[(eb + 2) * WRD + d] = v.z;
        wrt[(eb + 3) * WRD + d] = v.w;
    }
    __syncthreads();

    const int t = blockIdx.x * (RTB / 32) + (tid >> 5);
    const int lane = tid & 31;
    const float4* xr = reinterpret_cast<const float4*>(x + (size_t)t * DD);
    uint2* xo = reinterpret_cast<uint2*>(g_xf + (size_t)t * DD);

    float acc[EE];
    #pragma unroll
    for (int e = 0; e < EE; e++) acc[e] = 0.f;

    #pragma unroll
    for (int i = 0; i < 8; i++) {
        const int c = lane + i * 32;            // float4 index within row
        float4 v = xr[c];
        // fused fp16 conversion (coalesced 8B per lane)
        __half2 lo = __float22half2_rn(make_float2(v.x, v.y));
        __half2 hi = __float22half2_rn(make_float2(v.z, v.w));
        uint2 o;
        o.x = *reinterpret_cast<uint32_t*>(&lo);
        o.y = *reinterpret_cast<uint32_t*>(&hi);
        xo[c] = o;
        // logits: lanes read consecutive float4s of wrt[e] -> conflict-free
        #pragma unroll
        for (int e = 0; e < EE; e++) {
            const float4 wv = *reinterpret_cast<const float4*>(&wrt[e * WRD + c * 4]);
            acc[e] = fmaf(v.x, wv.x, acc[e]);
            acc[e] = fmaf(v.y, wv.y, acc[e]);
            acc[e] = fmaf(v.z, wv.z, acc[e]);
            acc[e] = fmaf(v.w, wv.w, acc[e]);
        }
    }
    #pragma unroll
    for (int off = 16; off; off >>= 1)
        #pragma unroll
        for (int e = 0; e < EE; e++)
            acc[e] += __shfl_xor_sync(0xffffffffu, acc[e], off);

    if (lane == 0) {
        #pragma unroll
        for (int e = 0; e < EE; e++) acc[e] += br[e];
        float v0 = -3.4e38f; int i0 = 0;
        #pragma unroll
        for (int e = 0; e < EE; e++) if (acc[e] > v0) { v0 = acc[e]; i0 = e; }
        float v1 = -3.4e38f; int i1 = 0;
        #pragma unroll
        for (int e = 0; e < EE; e++) if (e != i0 && acc[e] > v1) { v1 = acc[e]; i1 = e; }
        float eb  = expf(v1 - v0);
        float inv = 1.f / (1.f + eb);
        int p0 = atomicAdd(&g_cnt[i0], 1);
        g_tok[i0 * CAP + p0] = t; g_gate[i0 * CAP + p0] = inv;
        int p1 = atomicAdd(&g_cnt[i1], 1);
        g_tok[i1 * CAP + p1] = t; g_gate[i1 * CAP + p1] = eb * inv;
    }
}

// ---------------- asm helpers ----------------
__device__ __forceinline__ void mma_f16(float c[4], const uint32_t a[4], const uint32_t b[2]) {
    asm volatile(
        "mma.sync.aligned.m16n8k16.row.col.f32.f16.f16.f32 "
        "{%0,%1,%2,%3}, {%4,%5,%6,%7}, {%8,%9}, {%0,%1,%2,%3};\n"
        : "+f"(c[0]), "+f"(c[1]), "+f"(c[2]), "+f"(c[3])
        : "r"(a[0]), "r"(a[1]), "r"(a[2]), "r"(a[3]), "r"(b[0]), "r"(b[1]));
}
__device__ __forceinline__ void ldsm_x4(uint32_t r[4], uint32_t addr) {
    asm volatile("ldmatrix.sync.aligned.m8n8.x4.shared.b16 {%0,%1,%2,%3}, [%4];\n"
        : "=r"(r[0]), "=r"(r[1]), "=r"(r[2]), "=r"(r[3]) : "r"(addr));
}
__device__ __forceinline__ void ldsm_x4_t(uint32_t r[4], uint32_t addr) {
    asm volatile("ldmatrix.sync.aligned.m8n8.x4.trans.shared.b16 {%0,%1,%2,%3}, [%4];\n"
        : "=r"(r[0]), "=r"(r[1]), "=r"(r[2]), "=r"(r[3]) : "r"(addr));
}
__device__ __forceinline__ void cp16(uint32_t dst, const void* src) {
    asm volatile("cp.async.cg.shared.global [%0], [%1], 16;\n" :: "r"(dst), "l"(src));
}
__device__ __forceinline__ void cp16z(uint32_t dst, const void* src, uint32_t sz) {
    asm volatile("cp.async.cg.shared.global [%0], [%1], 16, %2;\n" :: "r"(dst), "l"(src), "r"(sz));
}
__device__ __forceinline__ void red_v2(float* addr, float v0, float v1) {
    asm volatile("red.global.add.v2.f32 [%0], {%1, %2};\n"
        :: "l"(addr), "f"(v0), "f"(v1) : "memory");
}
#define CP_COMMIT() asm volatile("cp.async.commit_group;\n")
#define CP_WAIT2()  asm volatile("cp.async.wait_group 2;\n")

// ---------------- GEMM1: H = relu(Xg @ W1 + b1), fp16 MMA, 4-stage pipe ----------------
__global__ __launch_bounds__(NT, 2) void k_gemm1(const float* __restrict__ b1) {
    const int e   = blockIdx.z;
    const int cnt = g_cnt[e];
    const int mb  = blockIdx.y * BM;
    if (mb >= cnt) return;
    const int nb  = blockIdx.x * BN;

    extern __shared__ char dynsmem[];
    const uint32_t sA = (uint32_t)__cvta_generic_to_shared(dynsmem);
    const uint32_t sB = sA + NSTG * ASTB;
    __shared__ int stok[BM];

    const int tid = threadIdx.x;
    if (tid < BM) {
        int m = mb + tid;
        stok[tid] = (m < cnt) ? g_tok[e * CAP + m] : -1;
    }
    __syncthreads();

    const int a_row = tid >> 1;
    const int a_col = (tid & 1) * 16;
    const int b_kr  = tid >> 3;
    const int b_nc  = (tid & 7) * 16;
    const int atok  = stok[a_row];
    const uint32_t a_sz = (atok >= 0) ? 16u : 0u;
    const __half* agp = g_xf + (atok >= 0 ? (size_t)atok * DD + a_col : 0);
    const __half* wbp = g_w1f + (size_t)e * DD * HH + (size_t)b_kr * HH + nb + b_nc;
    const uint32_t aoff = (a_row * LDAS + a_col) * 2;
    const uint32_t boff = (b_kr * LDBS + b_nc) * 2;

    const int w = tid >> 5, lane = tid & 31;
    const int wm = (w >> 2) * 64, wn = (w & 3) * 32;
    const int g = lane >> 2, tq = lane & 3;
    const int alr = lane & 15, ahc = (lane >> 4) * 8;
    uint32_t aoffs[4], boffs[2];
    #pragma unroll
    for (int mf = 0; mf < 4; mf++)
        aoffs[mf] = ((wm + mf * 16 + alr) * LDAS + ahc) * 2;
    #pragma unroll
    for (int ns = 0; ns < 2; ns++)
        boffs[ns] = (alr * LDBS + wn + ns * 16 + ahc) * 2;

    float acc[4][4][4];
    #pragma unroll
    for (int a = 0; a < 4; a++)
        #pragma unroll
        for (int b = 0; b < 4; b++)
            #pragma unroll
            for (int c = 0; c < 4; c++) acc[a][b][c] = 0.f;

    const int NS = DD / BK;   // 32
    #pragma unroll
    for (int p = 0; p < NSTG - 1; p++) {
        const int kt = p * BK;
        const uint32_t ao = p * ASTB + aoff, bo = p * BSTB + boff;
        cp16z(sA + ao, agp + kt, a_sz);
        cp16z(sA + ao + 16, agp + kt + 8, a_sz);
        cp16(sB + bo, wbp + (size_t)kt * HH);
        cp16(sB + bo + 16, wbp + (size_t)kt * HH + 8);
        CP_COMMIT();
    }
    for (int s = 0; s < NS; s++) {
        CP_WAIT2();
        __syncthreads();
        if (s + NSTG - 1 < NS) {
            const int p = s + NSTG - 1;
            const int kt = p * BK;
            const uint32_t ao = (p & 3) * ASTB + aoff, bo = (p & 3) * BSTB + boff;
            cp16z(sA + ao, agp + kt, a_sz);
            cp16z(sA + ao + 16, agp + kt + 8, a_sz);
            cp16(sB + bo, wbp + (size_t)kt * HH);
            cp16(sB + bo + 16, wbp + (size_t)kt * HH + 8);
        }
        CP_COMMIT();

        const uint32_t Ab = sA + (s & 3) * ASTB;
        const uint32_t Bb = sB + (s & 3) * BSTB;
        #pragma unroll
        for (int kk = 0; kk < BK; kk += 16) {
            uint32_t ah[4][4], bfr[2][4];
            #pragma unroll
            for (int mf = 0; mf < 4; mf++) ldsm_x4(ah[mf], Ab + aoffs[mf] + kk * 2);
            #pragma unroll
            for (int ns = 0; ns < 2; ns++) ldsm_x4_t(bfr[ns], Bb + boffs[ns] + kk * (LDBS * 2));
            #pragma unroll
            for (int mf = 0; mf < 4; mf++)
                #pragma unroll
                for (int nf = 0; nf < 4; nf++)
                    mma_f16(acc[mf][nf], ah[mf], &bfr[nf >> 1][(nf & 1) * 2]);
        }
    }

    // epilogue: +b1, relu, store fp16 h
    #pragma unroll
    for (int mf = 0; mf < 4; mf++) {
        #pragma unroll
        for (int rr = 0; rr < 2; rr++) {
            int m = mb + wm + mf * 16 + g + rr * 8;
            if (m >= cnt) continue;
            size_t base = ((size_t)e * CAP + m) * HH + nb;
            #pragma unroll
            for (int nf = 0; nf < 4; nf++) {
                int c = wn + nf * 8 + 2 * tq;
                float v0 = fmaxf(acc[mf][nf][rr * 2 + 0] + b1[e * HH + nb + c], 0.f);
                float v1 = fmaxf(acc[mf][nf][rr * 2 + 1] + b1[e * HH + nb + c + 1], 0.f);
                __half2 pr = __float22half2_rn(make_float2(v0, v1));
                *reinterpret_cast<__half2*>(&g_hf[base + c]) = pr;
            }
        }
    }
}

// ---------------- GEMM2: out += gate * (H @ W2 + b2), fp16 MMA, red.v2 epilogue ----------------
__global__ __launch_bounds__(NT, 2) void k_gemm2(const float* __restrict__ b2,
                                                 float* __restrict__ out) {
    const int e   = blockIdx.z;
    const int cnt = g_cnt[e];
    const int mb  = blockIdx.y * BM;
    if (mb >= cnt) return;
    const int nb  = blockIdx.x * BN;

    extern __shared__ char dynsmem[];
    const uint32_t sA = (uint32_t)__cvta_generic_to_shared(dynsmem);
    const uint32_t sB = sA + NSTG * ASTB;

    const int tid = threadIdx.x;
    const int a_row = tid >> 1;
    const int a_col = (tid & 1) * 16;
    const int b_kr  = tid >> 3;
    const int b_nc  = (tid & 7) * 16;
    // rows >= cnt read stale-but-finite scratch; their outputs are never stored
    const __half* agp = g_hf + ((size_t)e * CAP + mb + a_row) * HH + a_col;
    const __half* wbp = g_w2f + (size_t)e * HH * DD + (size_t)b_kr * DD + nb + b_nc;
    const uint32_t aoff = (a_row * LDAS + a_col) * 2;
    const uint32_t boff = (b_kr * LDBS + b_nc) * 2;

    const int w = tid >> 5, lane = tid & 31;
    const int wm = (w >> 2) * 64, wn = (w & 3) * 32;
    const int g = lane >> 2, tq = lane & 3;
    const int alr = lane & 15, ahc = (lane >> 4) * 8;
    uint32_t aoffs[4], boffs[2];
    #pragma unroll
    for (int mf = 0; mf < 4; mf++)
        aoffs[mf] = ((wm + mf * 16 + alr) * LDAS + ahc) * 2;
    #pragma unroll
    for (int ns = 0; ns < 2; ns++)
        boffs[ns] = (alr * LDBS + wn + ns * 16 + ahc) * 2;

    float acc[4][4][4];
    #pragma unroll
    for (int a = 0; a < 4; a++)
        #pragma unroll
        for (int b = 0; b < 4; b++)
            #pragma unroll
            for (int c = 0; c < 4; c++) acc[a][b][c] = 0.f;

    const int NS = HH / BK;   // 64
    #pragma unroll
    for (int p = 0; p < NSTG - 1; p++) {
        const int kt = p * BK;
        const uint32_t ao = p * ASTB + aoff, bo = p * BSTB + boff;
        cp16(sA + ao, agp + kt);
        cp16(sA + ao + 16, agp + kt + 8);
        cp16(sB + bo, wbp + (size_t)kt * DD);
        cp16(sB + bo + 16, wbp + (size_t)kt * DD + 8);
        CP_COMMIT();
    }
    for (int s = 0; s < NS; s++) {
        CP_WAIT2();
        __syncthreads();
        if (s + NSTG - 1 < NS) {
            const int p = s + NSTG - 1;
            const int kt = p * BK;
            const uint32_t ao = (p & 3) * ASTB + aoff, bo = (p & 3) * BSTB + boff;
            cp16(sA + ao, agp + kt);
            cp16(sA + ao + 16, agp + kt + 8);
            cp16(sB + bo, wbp + (size_t)kt * DD);
            cp16(sB + bo + 16, wbp + (size_t)kt * DD + 8);
        }
        CP_COMMIT();

        const uint32_t Ab = sA + (s & 3) * ASTB;
        const uint32_t Bb = sB + (s & 3) * BSTB;
        #pragma unroll
        for (int kk = 0; kk < BK; kk += 16) {
            uint32_t ah[4][4], bfr[2][4];
            #pragma unroll
            for (int mf = 0; mf < 4; mf++) ldsm_x4(ah[mf], Ab + aoffs[mf] + kk * 2);
            #pragma unroll
            for (int ns = 0; ns < 2; ns++) ldsm_x4_t(bfr[ns], Bb + boffs[ns] + kk * (LDBS * 2));
            #pragma unroll
            for (int mf = 0; mf < 4; mf++)
                #pragma unroll
                for (int nf = 0; nf < 4; nf++)
                    mma_f16(acc[mf][nf], ah[mf], &bfr[nf >> 1][(nf & 1) * 2]);
        }
    }

    // epilogue: +b2, * gate, vector red into out (2 expert contributions per token)
    #pragma unroll
    for (int mf = 0; mf < 4; mf++) {
        #pragma unroll
        for (int rr = 0; rr < 2; rr++) {
            int m = mb + wm + mf * 16 + g + rr * 8;
            if (m >= cnt) continue;
            float gate = g_gate[e * CAP + m];
            int   tokid = g_tok[e * CAP + m];
            float* orow = out + (size_t)tokid * DD + nb;
            #pragma unroll
            for (int nf = 0; nf < 4; nf++) {
                int c = wn + nf * 8 + 2 * tq;
                red_v2(&orow[c],
                       (acc[mf][nf][rr * 2 + 0] + b2[e * DD + nb + c]) * gate,
                       (acc[mf][nf][rr * 2 + 1] + b2[e * DD + nb + c + 1]) * gate);
            }
        }
    }
}

// ---------------- launch ----------------
extern "C" void kernel_launch(void* const* d_in, const int* in_sizes, int n_in,
                              void* d_out, int out_size) {
    const float* x  = (const float*)d_in[0];
    const float* Wr = (const float*)d_in[1];
    const float* br = (const float*)d_in[2];
    const float* W1 = (const float*)d_in[3];
    const float* b1 = (const float*)d_in[4];
    const float* W2 = (const float*)d_in[5];
    const float* b2 = (const float*)d_in[6];
    float* out = (float*)d_out;

    cudaFuncSetAttribute(k_gemm1, cudaFuncAttributeMaxDynamicSharedMemorySize, SMEM_DYN);
    cudaFuncSetAttribute(k_gemm2, cudaFuncAttributeMaxDynamicSharedMemorySize, SMEM_DYN);

    k_zout<<<(NTOK * DD / 4) / 256, 256>>>(out);            // 1
    k_cvt<<<4096, 256>>>(W1, 1, EE * DD * HH / 4);          // 2
    k_cvt<<<4096, 256>>>(W2, 2, EE * HH * DD / 4);          // 3
    k_router<<<NTOK / (RTB / 32), RTB>>>(x, Wr, br);        // 4
    k_gemm1<<<dim3(HH / BN, CAP / BM, EE), NT, SMEM_DYN>>>(b1);        // 5
    k_gemm2<<<dim3(DD / BN, CAP / BM, EE), NT, SMEM_DYN>>>(b2, out);   // 6
}